// round 9
// baseline (speedup 1.0000x reference)
#include <cuda_runtime.h>
#include <cuda_bf16.h>
#include <math.h>
#include <stdint.h>

// ---------------------------------------------------------------------------
// RobustAttentionBlock (B=4, S=2048, E=1280, R=325, 3R=975) — mma.sync version
// (tcgen05 unavailable: harness targets baseline sm_100, not sm_100a)
//
// Re(FFT)/Re(IFFT) via radix-2 smem FFT (cos even => ReIFFT = ReFFT/2048).
// All GEMMs on mma.sync.m16n8k16 bf16 with 2-way split (hi+lo) and fp32
// accumulation: A@B ~= Ah@Bh + Ah@Bl + Al@Bh  (error ~2^-16).
// R8: 256x128 CTA tile, 64x64 warp tile, 3-stage cp.async pipeline,
//     reduced live-register inner loop (B frags resident, A per-mi).
// ---------------------------------------------------------------------------

#define EDIM   1280
#define SEQ    2048
#define BATCH  4
#define RANKD  325
#define RANKP  328          // padded K (zero-filled, 8-multiple)
#define N3R    975
#define BSROWS (BATCH * SEQ)

// ------------------------- fp32 scratch ------------------------------------
#define F_SC   0LL                               // scores / qkv_f temp
#define F_Q    (F_SC + 4LL*2048*2048)
#define F_K    (F_Q + 8192LL*1280)
#define F_V    (F_K + 8192LL*1280)
#define F_TW   (F_V + 8192LL*1280)
#define F_TOT  (F_TW + 2048LL)
__device__ float g_buf[F_TOT];

// ------------------------- bf16 scratch ------------------------------------
#define SZ_T   (8192LL*1280)
#define SZ_SC  (4LL*2048*2048)
#define H_XNH   0LL
#define H_XNL   (H_XNH + SZ_T)
#define H_WQKVH (H_XNL + SZ_T)
#define H_WQKVL (H_WQKVH + 975LL*1280)
#define H_QBH   (H_WQKVL + 975LL*1280)
#define H_QBL   (H_QBH + 8192LL*RANKP)
#define H_KBH   (H_QBL + 8192LL*RANKP)
#define H_KBL   (H_KBH + 8192LL*RANKP)
#define H_VBH   (H_KBL + 8192LL*RANKP)
#define H_VBL   (H_VBH + 8192LL*RANKP)
#define H_WQH   (H_VBL + 8192LL*RANKP)
#define H_WQL   (H_WQH + 1280LL*RANKP)
#define H_WKH   (H_WQL + 1280LL*RANKP)
#define H_WKL   (H_WKH + 1280LL*RANKP)
#define H_WVH   (H_WKL + 1280LL*RANKP)
#define H_WVL   (H_WVH + 1280LL*RANKP)
#define H_QFH   (H_WVL + 1280LL*RANKP)
#define H_QFL   (H_QFH + SZ_T)
#define H_KFH   (H_QFL + SZ_T)
#define H_KFL   (H_KFH + SZ_T)
#define H_VFH   (H_KFL + SZ_T)   // transposed: per batch 1280 x 2048
#define H_VFL   (H_VFH + SZ_T)
#define H_ATH   (H_VFL + SZ_T)
#define H_ATL   (H_ATH + SZ_SC)
#define H_AOH   (H_ATL + SZ_SC)
#define H_AOL   (H_AOH + SZ_T)
#define H_WOH   (H_AOL + SZ_T)
#define H_WOL   (H_WOH + 1280LL*1280)
#define H_TOT   (H_WOL + 1280LL*1280)
__device__ __nv_bfloat16 g_hb[H_TOT];

// ------------------------------ PTX helpers --------------------------------
__device__ __forceinline__ uint32_t smem_u32(const void* p) {
    uint32_t a;
    asm("{ .reg .u64 t; cvta.to.shared.u64 t, %1; cvt.u32.u64 %0, t; }"
        : "=r"(a) : "l"(p));
    return a;
}
__device__ __forceinline__ void cp_async16(uint32_t sa, const void* g, int ssz) {
    asm volatile("cp.async.ca.shared.global [%0], [%1], 16, %2;"
                 :: "r"(sa), "l"(g), "r"(ssz) : "memory");
}
__device__ __forceinline__ void cp_commit() {
    asm volatile("cp.async.commit_group;" ::: "memory");
}
template <int NG>
__device__ __forceinline__ void cp_wait() {
    asm volatile("cp.async.wait_group %0;" :: "n"(NG) : "memory");
}
__device__ __forceinline__ void ldm4(uint32_t* r, uint32_t a) {
    asm volatile("ldmatrix.sync.aligned.m8n8.x4.shared.b16 {%0,%1,%2,%3}, [%4];"
                 : "=r"(r[0]), "=r"(r[1]), "=r"(r[2]), "=r"(r[3]) : "r"(a));
}
__device__ __forceinline__ void ldm2(uint32_t* r, uint32_t a) {
    asm volatile("ldmatrix.sync.aligned.m8n8.x2.shared.b16 {%0,%1}, [%2];"
                 : "=r"(r[0]), "=r"(r[1]) : "r"(a));
}
__device__ __forceinline__ void mma16816(float* c, const uint32_t* a,
                                         const uint32_t* b) {
    asm volatile(
        "mma.sync.aligned.m16n8k16.row.col.f32.bf16.bf16.f32 "
        "{%0,%1,%2,%3}, {%4,%5,%6,%7}, {%8,%9}, {%0,%1,%2,%3};"
        : "+f"(c[0]), "+f"(c[1]), "+f"(c[2]), "+f"(c[3])
        : "r"(a[0]), "r"(a[1]), "r"(a[2]), "r"(a[3]), "r"(b[0]), "r"(b[1]));
}

__device__ __forceinline__ void split_bf(float v, __nv_bfloat16& h, __nv_bfloat16& l) {
    h = __float2bfloat16(v);
    l = __float2bfloat16(v - __bfloat162float(h));
}

// ------------------------------ reductions ---------------------------------
__device__ __forceinline__ float warpReduceSum(float v) {
    #pragma unroll
    for (int o = 16; o > 0; o >>= 1) v += __shfl_xor_sync(0xffffffffu, v, o);
    return v;
}
__device__ __forceinline__ float warpReduceMax(float v) {
    #pragma unroll
    for (int o = 16; o > 0; o >>= 1) v = fmaxf(v, __shfl_xor_sync(0xffffffffu, v, o));
    return v;
}

// ------------------------------ layernorm -> bf16 hi/lo --------------------
__global__ __launch_bounds__(256) void layernorm_kernel(
    const float* __restrict__ x, const float* __restrict__ gamma,
    const float* __restrict__ beta,
    __nv_bfloat16* __restrict__ yh, __nv_bfloat16* __restrict__ yl)
{
    long long row = blockIdx.x;
    const float* xr = x + row * EDIM;

    float s = 0.f, s2 = 0.f;
    for (int i = threadIdx.x; i < EDIM; i += 256) {
        float v = xr[i];
        s += v; s2 += v * v;
    }
    __shared__ float sh[64];
    s  = warpReduceSum(s);
    s2 = warpReduceSum(s2);
    int w = threadIdx.x >> 5, l = threadIdx.x & 31;
    if (l == 0) { sh[w] = s; sh[32 + w] = s2; }
    __syncthreads();
    if (w == 0) {
        float a = (l < 8) ? sh[l] : 0.f;
        float b = (l < 8) ? sh[32 + l] : 0.f;
        a = warpReduceSum(a);
        b = warpReduceSum(b);
        if (l == 0) { sh[0] = a; sh[1] = b; }
    }
    __syncthreads();
    float mean = sh[0] * (1.0f / EDIM);
    float var  = sh[1] * (1.0f / EDIM) - mean * mean;
    float inv  = rsqrtf(var + 1e-5f);
    for (int i = threadIdx.x; i < EDIM; i += 256) {
        float v = (xr[i] - mean) * inv * gamma[i] + beta[i];
        __nv_bfloat16 h, lo; split_bf(v, h, lo);
        yh[row * EDIM + i] = h;
        yl[row * EDIM + i] = lo;
    }
}

// ------------------------------ twiddles -----------------------------------
__global__ void fill_twiddle_kernel(float2* __restrict__ tw)
{
    int k = blockIdx.x * 256 + threadIdx.x;
    if (k < 1024) {
        double ang = -6.283185307179586476925286766559 * (double)k / 2048.0;
        tw[k] = make_float2((float)cos(ang), (float)sin(ang));
    }
}

// ------------------------- transpose + split (weights) ---------------------
__global__ __launch_bounds__(256) void transpose_split_kernel(
    const float* __restrict__ src, int R, int C,
    __nv_bfloat16* __restrict__ dh, __nv_bfloat16* __restrict__ dl, int dld)
{
    __shared__ float t[32][33];
    int c0 = blockIdx.x * 32, r0 = blockIdx.y * 32;
    int tx = threadIdx.x & 31, ty = threadIdx.x >> 5;
    for (int j = ty; j < 32; j += 8) {
        int y = r0 + j, xx = c0 + tx;
        t[j][tx] = (y < R && xx < C) ? src[(long long)y * C + xx] : 0.f;
    }
    __syncthreads();
    for (int j = ty; j < 32; j += 8) {
        int dr = c0 + j;
        int dc = r0 + tx;
        if (dr < C && dc < R) {
            __nv_bfloat16 h, lo; split_bf(t[tx][j], h, lo);
            dh[(long long)dr * dld + dc] = h;
            dl[(long long)dr * dld + dc] = lo;
        }
    }
}

// ------------------------- split qkv_f into q/k/v bufs ---------------------
__global__ __launch_bounds__(256) void split3_kernel(
    const float* __restrict__ qkvf,
    __nv_bfloat16* __restrict__ qh, __nv_bfloat16* __restrict__ ql,
    __nv_bfloat16* __restrict__ kh, __nv_bfloat16* __restrict__ kl,
    __nv_bfloat16* __restrict__ vh, __nv_bfloat16* __restrict__ vl)
{
    int c = blockIdx.x * 256 + threadIdx.x;
    if (c >= N3R) return;
    long long r = blockIdx.y;
    float v = qkvf[r * N3R + c];
    __nv_bfloat16 h, lo; split_bf(v, h, lo);
    int b = (c >= 650) ? 2 : (c >= 325 ? 1 : 0);
    int cc = c - b * 325;
    __nv_bfloat16* dh = (b == 0) ? qh : (b == 1 ? kh : vh);
    __nv_bfloat16* dl = (b == 0) ? ql : (b == 1 ? kl : vl);
    dh[r * RANKP + cc] = h;
    dl[r * RANKP + cc] = lo;
}

// ------------------------------ column FFT ---------------------------------
template <int OMODE>
__global__ __launch_bounds__(256) void fft_cols_kernel(
    const float* __restrict__ in,
    __nv_bfloat16* __restrict__ oh, __nv_bfloat16* __restrict__ ol,
    const float2* __restrict__ tw, float scale)
{
    __shared__ float2 z1[SEQ];
    __shared__ float2 z2[SEQ];
    __shared__ float2 twz[1024];

    int col0 = blockIdx.x * 4;
    long long b = blockIdx.y;
    const float* src = in + b * SEQ * EDIM + col0;
    int tid = threadIdx.x;

    for (int i = tid; i < 1024; i += 256) twz[i] = tw[i];

    for (int r = tid; r < SEQ; r += 256) {
        float4 v = *reinterpret_cast<const float4*>(src + (long long)r * EDIM);
        int br = __brev((unsigned)r) >> 21;
        z1[br] = make_float2(v.x, v.y);
        z2[br] = make_float2(v.z, v.w);
    }
    __syncthreads();

    for (int s = 0; s < 11; s++) {
        int half = 1 << s;
        for (int bb = tid; bb < 1024; bb += 256) {
            int pos = bb & (half - 1);
            int i0 = ((bb >> s) << (s + 1)) + pos;
            int i1 = i0 + half;
            float2 w = twz[pos << (10 - s)];
            float2 a, c; float tr, ti;
            a = z1[i0]; c = z1[i1];
            tr = w.x * c.x - w.y * c.y;
            ti = w.x * c.y + w.y * c.x;
            z1[i0] = make_float2(a.x + tr, a.y + ti);
            z1[i1] = make_float2(a.x - tr, a.y - ti);
            a = z2[i0]; c = z2[i1];
            tr = w.x * c.x - w.y * c.y;
            ti = w.x * c.y + w.y * c.x;
            z2[i0] = make_float2(a.x + tr, a.y + ti);
            z2[i1] = make_float2(a.x - tr, a.y - ti);
        }
        __syncthreads();
    }

    float h = 0.5f * scale;
    for (int r = tid; r < SEQ; r += 256) {
        int rr = (SEQ - r) & (SEQ - 1);
        float o0 = h * (z1[r].x + z1[rr].x);
        float o1 = h * (z1[r].y + z1[rr].y);
        float o2 = h * (z2[r].x + z2[rr].x);
        float o3 = h * (z2[r].y + z2[rr].y);
        __nv_bfloat16 h0,l0,h1,l1,h2,l2,h3,l3;
        split_bf(o0,h0,l0); split_bf(o1,h1,l1);
        split_bf(o2,h2,l2); split_bf(o3,h3,l3);
        if (OMODE == 0) {
            long long off = b * SEQ * EDIM + (long long)r * EDIM + col0;
            oh[off+0]=h0; oh[off+1]=h1; oh[off+2]=h2; oh[off+3]=h3;
            ol[off+0]=l0; ol[off+1]=l1; ol[off+2]=l2; ol[off+3]=l3;
        } else {
            long long ob = b * (long long)EDIM * SEQ;
            oh[ob + (long long)(col0+0)*SEQ + r] = h0;
            oh[ob + (long long)(col0+1)*SEQ + r] = h1;
            oh[ob + (long long)(col0+2)*SEQ + r] = h2;
            oh[ob + (long long)(col0+3)*SEQ + r] = h3;
            ol[ob + (long long)(col0+0)*SEQ + r] = l0;
            ol[ob + (long long)(col0+1)*SEQ + r] = l1;
            ol[ob + (long long)(col0+2)*SEQ + r] = l2;
            ol[ob + (long long)(col0+3)*SEQ + r] = l3;
        }
    }
}

// ------------------------------ abs-softmax -> bf16 hi/lo ------------------
__global__ __launch_bounds__(256) void softmax_abs_kernel(
    const float* __restrict__ s,
    __nv_bfloat16* __restrict__ ah, __nv_bfloat16* __restrict__ al)
{
    long long row = blockIdx.x;
    const float* sr = s + row * (long long)SEQ;
    float vals[8];
    float mx = -1e30f;
    #pragma unroll
    for (int i = 0; i < 8; i++) {
        float v = fabsf(sr[threadIdx.x + i * 256]);
        vals[i] = v;
        mx = fmaxf(mx, v);
    }
    __shared__ float sh[32];
    mx = warpReduceMax(mx);
    int w = threadIdx.x >> 5, l = threadIdx.x & 31;
    if (l == 0) sh[w] = mx;
    __syncthreads();
    if (w == 0) {
        float a = (l < 8) ? sh[l] : -1e30f;
        a = warpReduceMax(a);
        if (l == 0) sh[0] = a;
    }
    __syncthreads();
    float M = sh[0];
    float sum = 0.f;
    #pragma unroll
    for (int i = 0; i < 8; i++) {
        vals[i] = expf(vals[i] - M);
        sum += vals[i];
    }
    __syncthreads();
    sum = warpReduceSum(sum);
    if (l == 0) sh[w] = sum;
    __syncthreads();
    if (w == 0) {
        float a = (l < 8) ? sh[l] : 0.f;
        a = warpReduceSum(a);
        if (l == 0) sh[0] = a;
    }
    __syncthreads();
    float inv = 1.0f / sh[0];
    #pragma unroll
    for (int i = 0; i < 8; i++) {
        float v = vals[i] * inv;
        __nv_bfloat16 h, lo; split_bf(v, h, lo);
        long long off = row * (long long)SEQ + threadIdx.x + i * 256;
        ah[off] = h;
        al[off] = lo;
    }
}

// ------------------------------ HMMA GEMM ----------------------------------
// C[M,N] = alpha * (Ah+Al)[M,K] @ (Bh+Bl)[N,K]^T (+ Res), lo*lo dropped.
// 256x128 CTA tile, BK=32, 8 warps (4x2), warp tile 64x64.
// Smem rows padded to 80B (ldmatrix conflict-free). 3-stage cp.async.
// Inner loop keeps B fragments resident; A fragments loaded per-mi to cap
// live registers (~180 < 255, no spill).
// Requires M % 256 == 0 (true for all call sites: 8192, 2048).
#define BKC     32
#define ROWB    80
#define A_TB    (256 * ROWB)             // 20480
#define B_TB    (128 * ROWB)             // 10240
#define STAGEB  (2 * A_TB + 2 * B_TB)    // 61440
#define GEMM_SMEM (3 * STAGEB)           // 184320

template <int ROWS>
__device__ __forceinline__ void load_tile_async(
    uint32_t tb, const __nv_bfloat16* __restrict__ src, long long row0,
    int ld, int nvalid, int kbase, int K, int tid)
{
    #pragma unroll
    for (int j = 0; j < ROWS / 64; j++) {
        int row = (tid >> 2) + j * 64;
        int c = tid & 3;
        uint32_t sa = tb + row * ROWB + c * 16;
        const __nv_bfloat16* g = src + (row0 + row) * (long long)ld + kbase + c * 8;
        int ssz = (row < nvalid && (kbase + c * 8) < K) ? 16 : 0;
        cp_async16(sa, g, ssz);
    }
}

__device__ __forceinline__ void load_stage(
    uint32_t tb,
    const __nv_bfloat16* Ah, const __nv_bfloat16* Al, long long m0, int lda,
    const __nv_bfloat16* Bh, const __nv_bfloat16* Bl, int n0, int ldb,
    int nvB, int kb, int K, int tid)
{
    load_tile_async<256>(tb,                Ah, m0, lda, 256, kb, K, tid);
    load_tile_async<256>(tb + A_TB,         Al, m0, lda, 256, kb, K, tid);
    load_tile_async<128>(tb + 2 * A_TB,     Bh, n0, ldb, nvB, kb, K, tid);
    load_tile_async<128>(tb + 2 * A_TB + B_TB, Bl, n0, ldb, nvB, kb, K, tid);
}

__global__ void __launch_bounds__(256, 1) hmma_gemm_kernel(
    const __nv_bfloat16* __restrict__ Ah, const __nv_bfloat16* __restrict__ Al,
    int lda, long long sA,
    const __nv_bfloat16* __restrict__ Bh, const __nv_bfloat16* __restrict__ Bl,
    int ldb, long long sB,
    float* __restrict__ C, int ldc, long long sC,
    int M, int N, int K, float alpha,
    const float* __restrict__ Res, long long sRes)
{
    extern __shared__ char smem[];
    uint32_t sb = smem_u32(smem);
    int tid = threadIdx.x;
    int lane = tid & 31, w = tid >> 5;
    int wm = w & 3, wn = w >> 2;   // 4 x 2 warp grid, warp tile 64x64

    long long bz = blockIdx.z;
    Ah += bz * sA; Al += bz * sA;
    Bh += bz * sB; Bl += bz * sB;
    C  += bz * sC;
    if (Res) Res += bz * sRes;

    long long m0 = (long long)blockIdx.y * 256;
    int n0 = blockIdx.x * 128;
    int nvB = N - n0; if (nvB > 128) nvB = 128;

    float acc[4][8][4];
    #pragma unroll
    for (int i = 0; i < 4; i++)
        #pragma unroll
        for (int j = 0; j < 8; j++)
            #pragma unroll
            for (int e = 0; e < 4; e++) acc[i][j][e] = 0.f;

    int l16 = lane & 15;
    uint32_t offA = (uint32_t)((wm * 64 + l16) * ROWB + ((lane >> 4) & 1) * 16);
    uint32_t offB = (uint32_t)((wn * 64 + (l16 & 7)) * ROWB + ((l16 >> 3) & 1) * 16);

    int nch = (K + BKC - 1) / BKC;

    // prologue: stages 0, 1
    load_stage(sb, Ah, Al, m0, lda, Bh, Bl, n0, ldb, nvB, 0, K, tid);
    cp_commit();
    if (nch > 1) {
        load_stage(sb + STAGEB, Ah, Al, m0, lda, Bh, Bl, n0, ldb, nvB,
                   BKC, K, tid);
    }
    cp_commit();

    int st = 0;
    for (int kt = 0; kt < nch; kt++) {
        if (kt + 2 < nch) {
            int st2 = st + 2; if (st2 >= 3) st2 -= 3;
            load_stage(sb + st2 * STAGEB, Ah, Al, m0, lda, Bh, Bl, n0, ldb,
                       nvB, (kt + 2) * BKC, K, tid);
            cp_commit();
            cp_wait<2>();
        } else if (kt + 1 < nch) {
            cp_wait<1>();
        } else {
            cp_wait<0>();
        }
        __syncthreads();

        uint32_t tb = sb + st * STAGEB;
        #pragma unroll
        for (int ks = 0; ks < 2; ks++) {
            uint32_t kf = (uint32_t)(ks * 32);
            // B fragments resident for this ks
            uint32_t brH[8][2], brL[8][2];
            #pragma unroll
            for (int ni = 0; ni < 8; ni++) {
                uint32_t a = tb + 2 * A_TB + offB + (uint32_t)(ni * 8 * ROWB) + kf;
                ldm2(brH[ni], a);
                ldm2(brL[ni], a + B_TB);
            }
            // A fragments per-mi (caps live registers)
            #pragma unroll
            for (int mi = 0; mi < 4; mi++) {
                uint32_t arH[4], arL[4];
                uint32_t a = tb + offA + (uint32_t)(mi * 16 * ROWB) + kf;
                ldm4(arH, a);
                ldm4(arL, a + A_TB);
                #pragma unroll
                for (int ni = 0; ni < 8; ni++) {
                    mma16816(acc[mi][ni], arH, brH[ni]);
                    mma16816(acc[mi][ni], arH, brL[ni]);
                    mma16816(acc[mi][ni], arL, brH[ni]);
                }
            }
        }
        __syncthreads();
        st++; if (st >= 3) st = 0;
    }

    // epilogue: registers -> gmem
    #pragma unroll
    for (int mi = 0; mi < 4; mi++) {
        long long r0 = m0 + wm * 64 + mi * 16 + (lane >> 2);
        #pragma unroll
        for (int ni = 0; ni < 8; ni++) {
            int col = n0 + wn * 64 + ni * 8 + (lane & 3) * 2;
            float* a = acc[mi][ni];
            if (col < N) {
                long long o0 = r0 * (long long)ldc + col;
                long long o1 = (r0 + 8) * (long long)ldc + col;
                float v0 = alpha * a[0], v2 = alpha * a[2];
                if (Res) { v0 += Res[o0]; v2 += Res[o1]; }
                C[o0] = v0; C[o1] = v2;
                if (col + 1 < N) {
                    float v1 = alpha * a[1], v3 = alpha * a[3];
                    if (Res) { v1 += Res[o0 + 1]; v3 += Res[o1 + 1]; }
                    C[o0 + 1] = v1; C[o1 + 1] = v3;
                }
            }
        }
    }
}

// ------------------------------ host side ----------------------------------
static inline void run_mma(const __nv_bfloat16* Ah, const __nv_bfloat16* Al,
                           int lda, long long sA,
                           const __nv_bfloat16* Bh, const __nv_bfloat16* Bl,
                           int ldb, long long sB,
                           float* C, int ldc, long long sC,
                           int M, int N, int K, float alpha,
                           const float* Res, long long sRes, int nb)
{
    dim3 grid((N + 127) / 128, (M + 255) / 256, nb);
    hmma_gemm_kernel<<<grid, 256, GEMM_SMEM>>>(Ah, Al, lda, sA, Bh, Bl, ldb, sB,
                                               C, ldc, sC, M, N, K, alpha,
                                               Res, sRes);
}

extern "C" void kernel_launch(void* const* d_in, const int* in_sizes, int n_in,
                              void* d_out, int out_size)
{
    const float* x     = (const float*)d_in[0];  // (4,2048,1280)
    const float* Wqkv  = (const float*)d_in[1];  // (1280,975)
    const float* Wq    = (const float*)d_in[2];  // (325,1280)
    const float* Wk    = (const float*)d_in[3];  // (325,1280)
    const float* Wv    = (const float*)d_in[4];  // (325,1280)
    const float* Wout  = (const float*)d_in[5];  // (1280,1280)
    const float* gamma = (const float*)d_in[6];
    const float* beta  = (const float*)d_in[7];
    float* out = (float*)d_out;                  // (4,2048,1280)

    static int smem_set = 0;
    if (!smem_set) {
        cudaFuncSetAttribute(hmma_gemm_kernel,
                             cudaFuncAttributeMaxDynamicSharedMemorySize,
                             GEMM_SMEM);
        smem_set = 1;
    }

    float* fb = nullptr;
    __nv_bfloat16* hb = nullptr;
    cudaGetSymbolAddress((void**)&fb, g_buf);
    cudaGetSymbolAddress((void**)&hb, g_hb);

    float*  scores = fb + F_SC;       // also qkv_f temp
    float*  q      = fb + F_Q;        // also out_fft
    float*  k      = fb + F_K;
    float*  v      = fb + F_V;
    float2* tw     = (float2*)(fb + F_TW);

    const long long sT = (long long)SEQ * EDIM;
    const long long sS = (long long)SEQ * SEQ;
    const float scale = 0.07905694150420949f;   // 1/sqrt(160)

    // 1. LayerNorm -> xn hi/lo; twiddles; weight transposes+splits
    layernorm_kernel<<<BSROWS, 256>>>(x, gamma, beta, hb + H_XNH, hb + H_XNL);
    fill_twiddle_kernel<<<4, 256>>>(tw);
    {
        dim3 b(256);
        transpose_split_kernel<<<dim3((975 + 31) / 32, (1280 + 31) / 32), b>>>(
            Wqkv, 1280, 975, hb + H_WQKVH, hb + H_WQKVL, 1280);
        transpose_split_kernel<<<dim3((1280 + 31) / 32, (325 + 31) / 32), b>>>(
            Wq, 325, 1280, hb + H_WQH, hb + H_WQL, RANKP);
        transpose_split_kernel<<<dim3((1280 + 31) / 32, (325 + 31) / 32), b>>>(
            Wk, 325, 1280, hb + H_WKH, hb + H_WKL, RANKP);
        transpose_split_kernel<<<dim3((1280 + 31) / 32, (325 + 31) / 32), b>>>(
            Wv, 325, 1280, hb + H_WVH, hb + H_WVL, RANKP);
        transpose_split_kernel<<<dim3(40, 40), b>>>(
            Wout, 1280, 1280, hb + H_WOH, hb + H_WOL, 1280);
    }

    // 2. qkv_f = xn @ Wqkv  (8192 x 975, K=1280)
    run_mma(hb + H_XNH, hb + H_XNL, EDIM, 0,
            hb + H_WQKVH, hb + H_WQKVL, EDIM, 0,
            scores, N3R, 0, BSROWS, N3R, EDIM, 1.f, nullptr, 0, 1);

    // 3. split qkv_f into q/k/v bf16 hi/lo (padded ld 328, pad stays zero)
    split3_kernel<<<dim3((N3R + 255) / 256, BSROWS), 256>>>(
        scores, hb + H_QBH, hb + H_QBL, hb + H_KBH, hb + H_KBL,
        hb + H_VBH, hb + H_VBL);

    // 4. q/k/v = qkv_slice @ W  (8192 x 1280, K=328 incl. zero pad)
    run_mma(hb + H_QBH, hb + H_QBL, RANKP, 0, hb + H_WQH, hb + H_WQL, RANKP, 0,
            q, EDIM, 0, BSROWS, EDIM, RANKP, 1.f, nullptr, 0, 1);
    run_mma(hb + H_KBH, hb + H_KBL, RANKP, 0, hb + H_WKH, hb + H_WKL, RANKP, 0,
            k, EDIM, 0, BSROWS, EDIM, RANKP, 1.f, nullptr, 0, 1);
    run_mma(hb + H_VBH, hb + H_VBL, RANKP, 0, hb + H_WVH, hb + H_WVL, RANKP, 0,
            v, EDIM, 0, BSROWS, EDIM, RANKP, 1.f, nullptr, 0, 1);

    // 5. FFT: qf/kf (row layout), vf (transposed for B of attn@V)
    {
        dim3 g(EDIM / 4, BATCH);
        fft_cols_kernel<0><<<g, 256>>>(q, hb + H_QFH, hb + H_QFL, tw, 1.0f);
        fft_cols_kernel<0><<<g, 256>>>(k, hb + H_KFH, hb + H_KFL, tw, 1.0f);
        fft_cols_kernel<1><<<g, 256>>>(v, hb + H_VFH, hb + H_VFL, tw, 1.0f);
    }

    // 6. scores = (qf @ kf^T) / sqrt(160)
    run_mma(hb + H_QFH, hb + H_QFL, EDIM, sT,
            hb + H_KFH, hb + H_KFL, EDIM, sT,
            scores, SEQ, sS, SEQ, SEQ, EDIM, scale, nullptr, 0, BATCH);

    // 7. attn = softmax(|scores|) -> bf16 hi/lo
    softmax_abs_kernel<<<BATCH * SEQ, 256>>>(scores, hb + H_ATH, hb + H_ATL);

    // 8. out_fft = attn @ vf  (B = vfT: 1280 x 2048 per batch) -> q scratch
    run_mma(hb + H_ATH, hb + H_ATL, SEQ, sS,
            hb + H_VFH, hb + H_VFL, SEQ, (long long)EDIM * SEQ,
            q, EDIM, sT, SEQ, EDIM, SEQ, 1.f, nullptr, 0, BATCH);

    // 9. attn_out = Re(FFT(out_fft))/2048 -> bf16 hi/lo
    {
        dim3 g(EDIM / 4, BATCH);
        fft_cols_kernel<0><<<g, 256>>>(q, hb + H_AOH, hb + H_AOL, tw,
                                       1.0f / 2048.0f);
    }

    // 10. out = x + attn_out @ W_out
    run_mma(hb + H_AOH, hb + H_AOL, EDIM, 0, hb + H_WOH, hb + H_WOL, EDIM, 0,
            out, EDIM, 0, BSROWS, EDIM, EDIM, 1.f, x, 0, 1);
}

// round 10
// speedup vs baseline: 1.0825x; 1.0825x over previous
#include <cuda_runtime.h>
#include <cuda_bf16.h>
#include <math.h>
#include <stdint.h>

// ---------------------------------------------------------------------------
// RobustAttentionBlock (B=4, S=2048, E=1280, R=325, 3R=975) — mma.sync version
// (tcgen05 unavailable: harness targets baseline sm_100, not sm_100a)
//
// Re(FFT)/Re(IFFT) via radix-2 smem FFT (cos even => ReIFFT = ReFFT/2048).
// All GEMMs on mma.sync.m16n8k16 bf16 with 2-way split (hi+lo) and fp32
// accumulation: A@B ~= Ah@Bh + Ah@Bl + Al@Bh  (error ~2^-16).
// R9: back to 128x128 CTA / 64x32 warp tile (R6 grid shapes; R8's 256-tile
//     lost to wave quantization), pass-major MMA ordering to break
//     same-accumulator RAW chains, 3-stage cp.async pipeline.
// ---------------------------------------------------------------------------

#define EDIM   1280
#define SEQ    2048
#define BATCH  4
#define RANKD  325
#define RANKP  328          // padded K (zero-filled, 8-multiple)
#define N3R    975
#define BSROWS (BATCH * SEQ)

// ------------------------- fp32 scratch ------------------------------------
#define F_SC   0LL                               // scores / qkv_f temp
#define F_Q    (F_SC + 4LL*2048*2048)
#define F_K    (F_Q + 8192LL*1280)
#define F_V    (F_K + 8192LL*1280)
#define F_TW   (F_V + 8192LL*1280)
#define F_TOT  (F_TW + 2048LL)
__device__ float g_buf[F_TOT];

// ------------------------- bf16 scratch ------------------------------------
#define SZ_T   (8192LL*1280)
#define SZ_SC  (4LL*2048*2048)
#define H_XNH   0LL
#define H_XNL   (H_XNH + SZ_T)
#define H_WQKVH (H_XNL + SZ_T)
#define H_WQKVL (H_WQKVH + 975LL*1280)
#define H_QBH   (H_WQKVL + 975LL*1280)
#define H_QBL   (H_QBH + 8192LL*RANKP)
#define H_KBH   (H_QBL + 8192LL*RANKP)
#define H_KBL   (H_KBH + 8192LL*RANKP)
#define H_VBH   (H_KBL + 8192LL*RANKP)
#define H_VBL   (H_VBH + 8192LL*RANKP)
#define H_WQH   (H_VBL + 8192LL*RANKP)
#define H_WQL   (H_WQH + 1280LL*RANKP)
#define H_WKH   (H_WQL + 1280LL*RANKP)
#define H_WKL   (H_WKH + 1280LL*RANKP)
#define H_WVH   (H_WKL + 1280LL*RANKP)
#define H_WVL   (H_WVH + 1280LL*RANKP)
#define H_QFH   (H_WVL + 1280LL*RANKP)
#define H_QFL   (H_QFH + SZ_T)
#define H_KFH   (H_QFL + SZ_T)
#define H_KFL   (H_KFH + SZ_T)
#define H_VFH   (H_KFL + SZ_T)   // transposed: per batch 1280 x 2048
#define H_VFL   (H_VFH + SZ_T)
#define H_ATH   (H_VFL + SZ_T)
#define H_ATL   (H_ATH + SZ_SC)
#define H_AOH   (H_ATL + SZ_SC)
#define H_AOL   (H_AOH + SZ_T)
#define H_WOH   (H_AOL + SZ_T)
#define H_WOL   (H_WOH + 1280LL*1280)
#define H_TOT   (H_WOL + 1280LL*1280)
__device__ __nv_bfloat16 g_hb[H_TOT];

// ------------------------------ PTX helpers --------------------------------
__device__ __forceinline__ uint32_t smem_u32(const void* p) {
    uint32_t a;
    asm("{ .reg .u64 t; cvta.to.shared.u64 t, %1; cvt.u32.u64 %0, t; }"
        : "=r"(a) : "l"(p));
    return a;
}
__device__ __forceinline__ void cp_async16(uint32_t sa, const void* g, int ssz) {
    asm volatile("cp.async.ca.shared.global [%0], [%1], 16, %2;"
                 :: "r"(sa), "l"(g), "r"(ssz) : "memory");
}
__device__ __forceinline__ void cp_commit() {
    asm volatile("cp.async.commit_group;" ::: "memory");
}
template <int NG>
__device__ __forceinline__ void cp_wait() {
    asm volatile("cp.async.wait_group %0;" :: "n"(NG) : "memory");
}
__device__ __forceinline__ void ldm4(uint32_t* r, uint32_t a) {
    asm volatile("ldmatrix.sync.aligned.m8n8.x4.shared.b16 {%0,%1,%2,%3}, [%4];"
                 : "=r"(r[0]), "=r"(r[1]), "=r"(r[2]), "=r"(r[3]) : "r"(a));
}
__device__ __forceinline__ void ldm2(uint32_t* r, uint32_t a) {
    asm volatile("ldmatrix.sync.aligned.m8n8.x2.shared.b16 {%0,%1}, [%2];"
                 : "=r"(r[0]), "=r"(r[1]) : "r"(a));
}
__device__ __forceinline__ void mma16816(float* c, const uint32_t* a,
                                         const uint32_t* b) {
    asm volatile(
        "mma.sync.aligned.m16n8k16.row.col.f32.bf16.bf16.f32 "
        "{%0,%1,%2,%3}, {%4,%5,%6,%7}, {%8,%9}, {%0,%1,%2,%3};"
        : "+f"(c[0]), "+f"(c[1]), "+f"(c[2]), "+f"(c[3])
        : "r"(a[0]), "r"(a[1]), "r"(a[2]), "r"(a[3]), "r"(b[0]), "r"(b[1]));
}

__device__ __forceinline__ void split_bf(float v, __nv_bfloat16& h, __nv_bfloat16& l) {
    h = __float2bfloat16(v);
    l = __float2bfloat16(v - __bfloat162float(h));
}

// ------------------------------ reductions ---------------------------------
__device__ __forceinline__ float warpReduceSum(float v) {
    #pragma unroll
    for (int o = 16; o > 0; o >>= 1) v += __shfl_xor_sync(0xffffffffu, v, o);
    return v;
}
__device__ __forceinline__ float warpReduceMax(float v) {
    #pragma unroll
    for (int o = 16; o > 0; o >>= 1) v = fmaxf(v, __shfl_xor_sync(0xffffffffu, v, o));
    return v;
}

// ------------------------------ layernorm -> bf16 hi/lo --------------------
__global__ __launch_bounds__(256) void layernorm_kernel(
    const float* __restrict__ x, const float* __restrict__ gamma,
    const float* __restrict__ beta,
    __nv_bfloat16* __restrict__ yh, __nv_bfloat16* __restrict__ yl)
{
    long long row = blockIdx.x;
    const float* xr = x + row * EDIM;

    float s = 0.f, s2 = 0.f;
    for (int i = threadIdx.x; i < EDIM; i += 256) {
        float v = xr[i];
        s += v; s2 += v * v;
    }
    __shared__ float sh[64];
    s  = warpReduceSum(s);
    s2 = warpReduceSum(s2);
    int w = threadIdx.x >> 5, l = threadIdx.x & 31;
    if (l == 0) { sh[w] = s; sh[32 + w] = s2; }
    __syncthreads();
    if (w == 0) {
        float a = (l < 8) ? sh[l] : 0.f;
        float b = (l < 8) ? sh[32 + l] : 0.f;
        a = warpReduceSum(a);
        b = warpReduceSum(b);
        if (l == 0) { sh[0] = a; sh[1] = b; }
    }
    __syncthreads();
    float mean = sh[0] * (1.0f / EDIM);
    float var  = sh[1] * (1.0f / EDIM) - mean * mean;
    float inv  = rsqrtf(var + 1e-5f);
    for (int i = threadIdx.x; i < EDIM; i += 256) {
        float v = (xr[i] - mean) * inv * gamma[i] + beta[i];
        __nv_bfloat16 h, lo; split_bf(v, h, lo);
        yh[row * EDIM + i] = h;
        yl[row * EDIM + i] = lo;
    }
}

// ------------------------------ twiddles -----------------------------------
__global__ void fill_twiddle_kernel(float2* __restrict__ tw)
{
    int k = blockIdx.x * 256 + threadIdx.x;
    if (k < 1024) {
        double ang = -6.283185307179586476925286766559 * (double)k / 2048.0;
        tw[k] = make_float2((float)cos(ang), (float)sin(ang));
    }
}

// ------------------------- transpose + split (weights) ---------------------
__global__ __launch_bounds__(256) void transpose_split_kernel(
    const float* __restrict__ src, int R, int C,
    __nv_bfloat16* __restrict__ dh, __nv_bfloat16* __restrict__ dl, int dld)
{
    __shared__ float t[32][33];
    int c0 = blockIdx.x * 32, r0 = blockIdx.y * 32;
    int tx = threadIdx.x & 31, ty = threadIdx.x >> 5;
    for (int j = ty; j < 32; j += 8) {
        int y = r0 + j, xx = c0 + tx;
        t[j][tx] = (y < R && xx < C) ? src[(long long)y * C + xx] : 0.f;
    }
    __syncthreads();
    for (int j = ty; j < 32; j += 8) {
        int dr = c0 + j;
        int dc = r0 + tx;
        if (dr < C && dc < R) {
            __nv_bfloat16 h, lo; split_bf(t[tx][j], h, lo);
            dh[(long long)dr * dld + dc] = h;
            dl[(long long)dr * dld + dc] = lo;
        }
    }
}

// ------------------------- split qkv_f into q/k/v bufs ---------------------
__global__ __launch_bounds__(256) void split3_kernel(
    const float* __restrict__ qkvf,
    __nv_bfloat16* __restrict__ qh, __nv_bfloat16* __restrict__ ql,
    __nv_bfloat16* __restrict__ kh, __nv_bfloat16* __restrict__ kl,
    __nv_bfloat16* __restrict__ vh, __nv_bfloat16* __restrict__ vl)
{
    int c = blockIdx.x * 256 + threadIdx.x;
    if (c >= N3R) return;
    long long r = blockIdx.y;
    float v = qkvf[r * N3R + c];
    __nv_bfloat16 h, lo; split_bf(v, h, lo);
    int b = (c >= 650) ? 2 : (c >= 325 ? 1 : 0);
    int cc = c - b * 325;
    __nv_bfloat16* dh = (b == 0) ? qh : (b == 1 ? kh : vh);
    __nv_bfloat16* dl = (b == 0) ? ql : (b == 1 ? kl : vl);
    dh[r * RANKP + cc] = h;
    dl[r * RANKP + cc] = lo;
}

// ------------------------------ column FFT ---------------------------------
template <int OMODE>
__global__ __launch_bounds__(256) void fft_cols_kernel(
    const float* __restrict__ in,
    __nv_bfloat16* __restrict__ oh, __nv_bfloat16* __restrict__ ol,
    const float2* __restrict__ tw, float scale)
{
    __shared__ float2 z1[SEQ];
    __shared__ float2 z2[SEQ];
    __shared__ float2 twz[1024];

    int col0 = blockIdx.x * 4;
    long long b = blockIdx.y;
    const float* src = in + b * SEQ * EDIM + col0;
    int tid = threadIdx.x;

    for (int i = tid; i < 1024; i += 256) twz[i] = tw[i];

    for (int r = tid; r < SEQ; r += 256) {
        float4 v = *reinterpret_cast<const float4*>(src + (long long)r * EDIM);
        int br = __brev((unsigned)r) >> 21;
        z1[br] = make_float2(v.x, v.y);
        z2[br] = make_float2(v.z, v.w);
    }
    __syncthreads();

    for (int s = 0; s < 11; s++) {
        int half = 1 << s;
        for (int bb = tid; bb < 1024; bb += 256) {
            int pos = bb & (half - 1);
            int i0 = ((bb >> s) << (s + 1)) + pos;
            int i1 = i0 + half;
            float2 w = twz[pos << (10 - s)];
            float2 a, c; float tr, ti;
            a = z1[i0]; c = z1[i1];
            tr = w.x * c.x - w.y * c.y;
            ti = w.x * c.y + w.y * c.x;
            z1[i0] = make_float2(a.x + tr, a.y + ti);
            z1[i1] = make_float2(a.x - tr, a.y - ti);
            a = z2[i0]; c = z2[i1];
            tr = w.x * c.x - w.y * c.y;
            ti = w.x * c.y + w.y * c.x;
            z2[i0] = make_float2(a.x + tr, a.y + ti);
            z2[i1] = make_float2(a.x - tr, a.y - ti);
        }
        __syncthreads();
    }

    float h = 0.5f * scale;
    for (int r = tid; r < SEQ; r += 256) {
        int rr = (SEQ - r) & (SEQ - 1);
        float o0 = h * (z1[r].x + z1[rr].x);
        float o1 = h * (z1[r].y + z1[rr].y);
        float o2 = h * (z2[r].x + z2[rr].x);
        float o3 = h * (z2[r].y + z2[rr].y);
        __nv_bfloat16 h0,l0,h1,l1,h2,l2,h3,l3;
        split_bf(o0,h0,l0); split_bf(o1,h1,l1);
        split_bf(o2,h2,l2); split_bf(o3,h3,l3);
        if (OMODE == 0) {
            long long off = b * SEQ * EDIM + (long long)r * EDIM + col0;
            oh[off+0]=h0; oh[off+1]=h1; oh[off+2]=h2; oh[off+3]=h3;
            ol[off+0]=l0; ol[off+1]=l1; ol[off+2]=l2; ol[off+3]=l3;
        } else {
            long long ob = b * (long long)EDIM * SEQ;
            oh[ob + (long long)(col0+0)*SEQ + r] = h0;
            oh[ob + (long long)(col0+1)*SEQ + r] = h1;
            oh[ob + (long long)(col0+2)*SEQ + r] = h2;
            oh[ob + (long long)(col0+3)*SEQ + r] = h3;
            ol[ob + (long long)(col0+0)*SEQ + r] = l0;
            ol[ob + (long long)(col0+1)*SEQ + r] = l1;
            ol[ob + (long long)(col0+2)*SEQ + r] = l2;
            ol[ob + (long long)(col0+3)*SEQ + r] = l3;
        }
    }
}

// ------------------------------ abs-softmax -> bf16 hi/lo ------------------
__global__ __launch_bounds__(256) void softmax_abs_kernel(
    const float* __restrict__ s,
    __nv_bfloat16* __restrict__ ah, __nv_bfloat16* __restrict__ al)
{
    long long row = blockIdx.x;
    const float* sr = s + row * (long long)SEQ;
    float vals[8];
    float mx = -1e30f;
    #pragma unroll
    for (int i = 0; i < 8; i++) {
        float v = fabsf(sr[threadIdx.x + i * 256]);
        vals[i] = v;
        mx = fmaxf(mx, v);
    }
    __shared__ float sh[32];
    mx = warpReduceMax(mx);
    int w = threadIdx.x >> 5, l = threadIdx.x & 31;
    if (l == 0) sh[w] = mx;
    __syncthreads();
    if (w == 0) {
        float a = (l < 8) ? sh[l] : -1e30f;
        a = warpReduceMax(a);
        if (l == 0) sh[0] = a;
    }
    __syncthreads();
    float M = sh[0];
    float sum = 0.f;
    #pragma unroll
    for (int i = 0; i < 8; i++) {
        vals[i] = expf(vals[i] - M);
        sum += vals[i];
    }
    __syncthreads();
    sum = warpReduceSum(sum);
    if (l == 0) sh[w] = sum;
    __syncthreads();
    if (w == 0) {
        float a = (l < 8) ? sh[l] : 0.f;
        a = warpReduceSum(a);
        if (l == 0) sh[0] = a;
    }
    __syncthreads();
    float inv = 1.0f / sh[0];
    #pragma unroll
    for (int i = 0; i < 8; i++) {
        float v = vals[i] * inv;
        __nv_bfloat16 h, lo; split_bf(v, h, lo);
        long long off = row * (long long)SEQ + threadIdx.x + i * 256;
        ah[off] = h;
        al[off] = lo;
    }
}

// ------------------------------ HMMA GEMM ----------------------------------
// C[M,N] = alpha * (Ah+Al)[M,K] @ (Bh+Bl)[N,K]^T (+ Res), lo*lo dropped.
// 128x128 CTA tile, BK=32, 8 warps (2x4), warp tile 64x32.
// Smem rows padded to 80B (ldmatrix conflict-free). 3-stage cp.async.
// MMA issue is pass-major (all HH, all HL, all LH) so same-accumulator
// reuses are 15 independent MMAs apart (no RAW stalls on the tensor pipe).
#define BKC     32
#define ROWB    80
#define T_TB    (128 * ROWB)             // 10240 per tile
#define STAGEB  (4 * T_TB)               // 40960
#define GEMM_SMEM (3 * STAGEB)           // 122880

__device__ __forceinline__ void load_tile_async(
    uint32_t tb, const __nv_bfloat16* __restrict__ src, long long row0,
    int ld, int nvalid, int kbase, int K, int tid)
{
    #pragma unroll
    for (int j = 0; j < 2; j++) {
        int row = (tid >> 2) + j * 64;
        int c = tid & 3;
        uint32_t sa = tb + row * ROWB + c * 16;
        const __nv_bfloat16* g = src + (row0 + row) * (long long)ld + kbase + c * 8;
        int ssz = (row < nvalid && (kbase + c * 8) < K) ? 16 : 0;
        cp_async16(sa, g, ssz);
    }
}

__device__ __forceinline__ void load_stage(
    uint32_t tb,
    const __nv_bfloat16* Ah, const __nv_bfloat16* Al, long long m0, int lda,
    const __nv_bfloat16* Bh, const __nv_bfloat16* Bl, int n0, int ldb,
    int nvB, int kb, int K, int tid)
{
    load_tile_async(tb,            Ah, m0, lda, 128, kb, K, tid);
    load_tile_async(tb + T_TB,     Al, m0, lda, 128, kb, K, tid);
    load_tile_async(tb + 2 * T_TB, Bh, n0, ldb, nvB, kb, K, tid);
    load_tile_async(tb + 3 * T_TB, Bl, n0, ldb, nvB, kb, K, tid);
}

__global__ void __launch_bounds__(256, 1) hmma_gemm_kernel(
    const __nv_bfloat16* __restrict__ Ah, const __nv_bfloat16* __restrict__ Al,
    int lda, long long sA,
    const __nv_bfloat16* __restrict__ Bh, const __nv_bfloat16* __restrict__ Bl,
    int ldb, long long sB,
    float* __restrict__ C, int ldc, long long sC,
    int M, int N, int K, float alpha,
    const float* __restrict__ Res, long long sRes)
{
    extern __shared__ char smem[];
    uint32_t sb = smem_u32(smem);
    int tid = threadIdx.x;
    int lane = tid & 31, w = tid >> 5;
    int wm = w & 1, wn = w >> 1;   // 2 x 4 warp grid, warp tile 64x32

    long long bz = blockIdx.z;
    Ah += bz * sA; Al += bz * sA;
    Bh += bz * sB; Bl += bz * sB;
    C  += bz * sC;
    if (Res) Res += bz * sRes;

    long long m0 = (long long)blockIdx.y * 128;
    int n0 = blockIdx.x * 128;
    int nvB = N - n0; if (nvB > 128) nvB = 128;

    float acc[4][4][4];
    #pragma unroll
    for (int i = 0; i < 4; i++)
        #pragma unroll
        for (int j = 0; j < 4; j++)
            #pragma unroll
            for (int e = 0; e < 4; e++) acc[i][j][e] = 0.f;

    int l16 = lane & 15;
    uint32_t offA = (uint32_t)((wm * 64 + l16) * ROWB + ((lane >> 4) & 1) * 16);
    uint32_t offB = (uint32_t)((wn * 32 + (l16 & 7)) * ROWB + ((l16 >> 3) & 1) * 16);

    int nch = (K + BKC - 1) / BKC;

    // prologue: stages 0, 1
    load_stage(sb, Ah, Al, m0, lda, Bh, Bl, n0, ldb, nvB, 0, K, tid);
    cp_commit();
    if (nch > 1) {
        load_stage(sb + STAGEB, Ah, Al, m0, lda, Bh, Bl, n0, ldb, nvB,
                   BKC, K, tid);
    }
    cp_commit();

    int st = 0;
    for (int kt = 0; kt < nch; kt++) {
        if (kt + 2 < nch) {
            int st2 = st + 2; if (st2 >= 3) st2 -= 3;
            load_stage(sb + st2 * STAGEB, Ah, Al, m0, lda, Bh, Bl, n0, ldb,
                       nvB, (kt + 2) * BKC, K, tid);
            cp_commit();
            cp_wait<2>();
        } else if (kt + 1 < nch) {
            cp_wait<1>();
        } else {
            cp_wait<0>();
        }
        __syncthreads();

        uint32_t tb = sb + st * STAGEB;
        #pragma unroll
        for (int ks = 0; ks < 2; ks++) {
            uint32_t kf = (uint32_t)(ks * 32);
            uint32_t arH[4][4], arL[4][4], brH[4][2], brL[4][2];
            #pragma unroll
            for (int mi = 0; mi < 4; mi++) {
                uint32_t a = tb + offA + (uint32_t)(mi * 16 * ROWB) + kf;
                ldm4(arH[mi], a);
                ldm4(arL[mi], a + T_TB);
            }
            #pragma unroll
            for (int ni = 0; ni < 4; ni++) {
                uint32_t a = tb + 2 * T_TB + offB + (uint32_t)(ni * 8 * ROWB) + kf;
                ldm2(brH[ni], a);
                ldm2(brL[ni], a + T_TB);
            }
            // pass-major: same acc touched once per pass of 16 MMAs
            #pragma unroll
            for (int mi = 0; mi < 4; mi++)
                #pragma unroll
                for (int ni = 0; ni < 4; ni++)
                    mma16816(acc[mi][ni], arH[mi], brH[ni]);
            #pragma unroll
            for (int mi = 0; mi < 4; mi++)
                #pragma unroll
                for (int ni = 0; ni < 4; ni++)
                    mma16816(acc[mi][ni], arH[mi], brL[ni]);
            #pragma unroll
            for (int mi = 0; mi < 4; mi++)
                #pragma unroll
                for (int ni = 0; ni < 4; ni++)
                    mma16816(acc[mi][ni], arL[mi], brH[ni]);
        }
        __syncthreads();
        st++; if (st >= 3) st = 0;
    }

    // epilogue: registers -> gmem
    #pragma unroll
    for (int mi = 0; mi < 4; mi++) {
        long long r0 = m0 + wm * 64 + mi * 16 + (lane >> 2);
        #pragma unroll
        for (int ni = 0; ni < 4; ni++) {
            int col = n0 + wn * 32 + ni * 8 + (lane & 3) * 2;
            float* a = acc[mi][ni];
            if (col < N) {
                long long o0 = r0 * (long long)ldc + col;
                long long o1 = (r0 + 8) * (long long)ldc + col;
                float v0 = alpha * a[0], v2 = alpha * a[2];
                if (Res) { v0 += Res[o0]; v2 += Res[o1]; }
                C[o0] = v0; C[o1] = v2;
                if (col + 1 < N) {
                    float v1 = alpha * a[1], v3 = alpha * a[3];
                    if (Res) { v1 += Res[o0 + 1]; v3 += Res[o1 + 1]; }
                    C[o0 + 1] = v1; C[o1 + 1] = v3;
                }
            }
        }
    }
}

// ------------------------------ host side ----------------------------------
static inline void run_mma(const __nv_bfloat16* Ah, const __nv_bfloat16* Al,
                           int lda, long long sA,
                           const __nv_bfloat16* Bh, const __nv_bfloat16* Bl,
                           int ldb, long long sB,
                           float* C, int ldc, long long sC,
                           int M, int N, int K, float alpha,
                           const float* Res, long long sRes, int nb)
{
    dim3 grid((N + 127) / 128, (M + 127) / 128, nb);
    hmma_gemm_kernel<<<grid, 256, GEMM_SMEM>>>(Ah, Al, lda, sA, Bh, Bl, ldb, sB,
                                               C, ldc, sC, M, N, K, alpha,
                                               Res, sRes);
}

extern "C" void kernel_launch(void* const* d_in, const int* in_sizes, int n_in,
                              void* d_out, int out_size)
{
    const float* x     = (const float*)d_in[0];  // (4,2048,1280)
    const float* Wqkv  = (const float*)d_in[1];  // (1280,975)
    const float* Wq    = (const float*)d_in[2];  // (325,1280)
    const float* Wk    = (const float*)d_in[3];  // (325,1280)
    const float* Wv    = (const float*)d_in[4];  // (325,1280)
    const float* Wout  = (const float*)d_in[5];  // (1280,1280)
    const float* gamma = (const float*)d_in[6];
    const float* beta  = (const float*)d_in[7];
    float* out = (float*)d_out;                  // (4,2048,1280)

    static int smem_set = 0;
    if (!smem_set) {
        cudaFuncSetAttribute(hmma_gemm_kernel,
                             cudaFuncAttributeMaxDynamicSharedMemorySize,
                             GEMM_SMEM);
        smem_set = 1;
    }

    float* fb = nullptr;
    __nv_bfloat16* hb = nullptr;
    cudaGetSymbolAddress((void**)&fb, g_buf);
    cudaGetSymbolAddress((void**)&hb, g_hb);

    float*  scores = fb + F_SC;       // also qkv_f temp
    float*  q      = fb + F_Q;        // also out_fft
    float*  k      = fb + F_K;
    float*  v      = fb + F_V;
    float2* tw     = (float2*)(fb + F_TW);

    const long long sT = (long long)SEQ * EDIM;
    const long long sS = (long long)SEQ * SEQ;
    const float scale = 0.07905694150420949f;   // 1/sqrt(160)

    // 1. LayerNorm -> xn hi/lo; twiddles; weight transposes+splits
    layernorm_kernel<<<BSROWS, 256>>>(x, gamma, beta, hb + H_XNH, hb + H_XNL);
    fill_twiddle_kernel<<<4, 256>>>(tw);
    {
        dim3 b(256);
        transpose_split_kernel<<<dim3((975 + 31) / 32, (1280 + 31) / 32), b>>>(
            Wqkv, 1280, 975, hb + H_WQKVH, hb + H_WQKVL, 1280);
        transpose_split_kernel<<<dim3((1280 + 31) / 32, (325 + 31) / 32), b>>>(
            Wq, 325, 1280, hb + H_WQH, hb + H_WQL, RANKP);
        transpose_split_kernel<<<dim3((1280 + 31) / 32, (325 + 31) / 32), b>>>(
            Wk, 325, 1280, hb + H_WKH, hb + H_WKL, RANKP);
        transpose_split_kernel<<<dim3((1280 + 31) / 32, (325 + 31) / 32), b>>>(
            Wv, 325, 1280, hb + H_WVH, hb + H_WVL, RANKP);
        transpose_split_kernel<<<dim3(40, 40), b>>>(
            Wout, 1280, 1280, hb + H_WOH, hb + H_WOL, 1280);
    }

    // 2. qkv_f = xn @ Wqkv  (8192 x 975, K=1280)
    run_mma(hb + H_XNH, hb + H_XNL, EDIM, 0,
            hb + H_WQKVH, hb + H_WQKVL, EDIM, 0,
            scores, N3R, 0, BSROWS, N3R, EDIM, 1.f, nullptr, 0, 1);

    // 3. split qkv_f into q/k/v bf16 hi/lo (padded ld 328, pad stays zero)
    split3_kernel<<<dim3((N3R + 255) / 256, BSROWS), 256>>>(
        scores, hb + H_QBH, hb + H_QBL, hb + H_KBH, hb + H_KBL,
        hb + H_VBH, hb + H_VBL);

    // 4. q/k/v = qkv_slice @ W  (8192 x 1280, K=328 incl. zero pad)
    run_mma(hb + H_QBH, hb + H_QBL, RANKP, 0, hb + H_WQH, hb + H_WQL, RANKP, 0,
            q, EDIM, 0, BSROWS, EDIM, RANKP, 1.f, nullptr, 0, 1);
    run_mma(hb + H_KBH, hb + H_KBL, RANKP, 0, hb + H_WKH, hb + H_WKL, RANKP, 0,
            k, EDIM, 0, BSROWS, EDIM, RANKP, 1.f, nullptr, 0, 1);
    run_mma(hb + H_VBH, hb + H_VBL, RANKP, 0, hb + H_WVH, hb + H_WVL, RANKP, 0,
            v, EDIM, 0, BSROWS, EDIM, RANKP, 1.f, nullptr, 0, 1);

    // 5. FFT: qf/kf (row layout), vf (transposed for B of attn@V)
    {
        dim3 g(EDIM / 4, BATCH);
        fft_cols_kernel<0><<<g, 256>>>(q, hb + H_QFH, hb + H_QFL, tw, 1.0f);
        fft_cols_kernel<0><<<g, 256>>>(k, hb + H_KFH, hb + H_KFL, tw, 1.0f);
        fft_cols_kernel<1><<<g, 256>>>(v, hb + H_VFH, hb + H_VFL, tw, 1.0f);
    }

    // 6. scores = (qf @ kf^T) / sqrt(160)
    run_mma(hb + H_QFH, hb + H_QFL, EDIM, sT,
            hb + H_KFH, hb + H_KFL, EDIM, sT,
            scores, SEQ, sS, SEQ, SEQ, EDIM, scale, nullptr, 0, BATCH);

    // 7. attn = softmax(|scores|) -> bf16 hi/lo
    softmax_abs_kernel<<<BATCH * SEQ, 256>>>(scores, hb + H_ATH, hb + H_ATL);

    // 8. out_fft = attn @ vf  (B = vfT: 1280 x 2048 per batch) -> q scratch
    run_mma(hb + H_ATH, hb + H_ATL, SEQ, sS,
            hb + H_VFH, hb + H_VFL, SEQ, (long long)EDIM * SEQ,
            q, EDIM, sT, SEQ, EDIM, SEQ, 1.f, nullptr, 0, BATCH);

    // 9. attn_out = Re(FFT(out_fft))/2048 -> bf16 hi/lo
    {
        dim3 g(EDIM / 4, BATCH);
        fft_cols_kernel<0><<<g, 256>>>(q, hb + H_AOH, hb + H_AOL, tw,
                                       1.0f / 2048.0f);
    }

    // 10. out = x + attn_out @ W_out
    run_mma(hb + H_AOH, hb + H_AOL, EDIM, 0, hb + H_WOH, hb + H_WOL, EDIM, 0,
            out, EDIM, 0, BSROWS, EDIM, EDIM, 1.f, x, 0, 1);
}

// round 12
// speedup vs baseline: 2.2709x; 2.0977x over previous
#include <cuda_runtime.h>
#include <cuda_bf16.h>
#include <math.h>
#include <stdint.h>

// ---------------------------------------------------------------------------
// RobustAttentionBlock (B=4, S=2048, E=1280, R=325) — rank-factored version
//
// FFT along seq commutes with feature projections:
//   scores = FFT(qa)·(Wq Wk^T)·FFT(ka)^T / sqrt(160)
//   out    = x + IFFT(attn·FFT(va)) · (Wv·W_out)
// so all attention-side GEMMs run at width R=325 (padded 328) instead of 1280.
// GEMMs: mma.sync bf16 2-way split (hi+lo), fp32 acc; err ~2^-16.
// ---------------------------------------------------------------------------

#define EDIM   1280
#define SEQ    2048
#define BATCH  4
#define RANKD  325
#define RANKP  328
#define N3R    975
#define BSROWS (BATCH * SEQ)

// ------------------------- fp32 scratch ------------------------------------
#define F_SC   0LL                                  // scores / qkv_f temp
#define F_QA   (F_SC  + 4LL*2048*2048)              // 8192 x 328
#define F_KA   (F_QA  + 8192LL*RANKP)
#define F_VA   (F_KA  + 8192LL*RANKP)
#define F_SM   (F_VA  + 8192LL*RANKP)               // 8192 x 328
#define F_Y    (F_SM  + 8192LL*RANKP)               // 4 x 2048 x 328
#define F_MQK  (F_Y   + 8192LL*RANKP)               // 325 x 325
#define F_WVO  (F_MQK + 105632LL)                   // 325 x 1280
#define F_TW   (F_WVO + 416000LL)
#define F_TOT  (F_TW  + 2048LL)
__device__ float g_buf[F_TOT];

// ------------------------- bf16 scratch ------------------------------------
#define SZ_T    (8192LL*1280)
#define SZ_R    (8192LL*RANKP)
#define SZ_SC   (4LL*2048*2048)
#define H_XNH    0LL
#define H_XNL    (H_XNH   + SZ_T)
#define H_WQKVH  (H_XNL   + SZ_T)
#define H_WQKVL  (H_WQKVH + 975LL*1280)
#define H_WQSH   (H_WQKVL + 975LL*1280)
#define H_WQSL   (H_WQSH  + 416000LL)
#define H_WKSH   (H_WQSL  + 416000LL)
#define H_WKSL   (H_WKSH  + 416000LL)
#define H_WVSH   (H_WKSL  + 416000LL)
#define H_WVSL   (H_WVSH  + 416000LL)
#define H_WOTH   (H_WVSL  + 416000LL)
#define H_WOTL   (H_WOTH  + 1280LL*1280)
#define H_MQKTH  (H_WOTL  + 1280LL*1280)
#define H_MQKTL  (H_MQKTH + 325LL*RANKP)
#define H_WVOTH  (H_MQKTL + 325LL*RANKP)
#define H_WVOTL  (H_WVOTH + 1280LL*RANKP)
#define H_QFAH   (H_WVOTL + 1280LL*RANKP)
#define H_QFAL   (H_QFAH  + SZ_R)
#define H_KFAH   (H_QFAL  + SZ_R)
#define H_KFAL   (H_KFAH  + SZ_R)
#define H_VFATH  (H_KFAL  + SZ_R)    // per batch: 328 x 2048
#define H_VFATL  (H_VFATH + SZ_R)
#define H_SMH    (H_VFATL + SZ_R)
#define H_SML    (H_SMH   + SZ_R)
#define H_ATH    (H_SML   + SZ_R)
#define H_ATL    (H_ATH   + SZ_SC)
#define H_ZH     (H_ATL   + SZ_SC)
#define H_ZL     (H_ZH    + SZ_R)
#define H_TOT    (H_ZL    + SZ_R)
__device__ __nv_bfloat16 g_hb[H_TOT];

// ------------------------------ PTX helpers --------------------------------
__device__ __forceinline__ uint32_t smem_u32(const void* p) {
    uint32_t a;
    asm("{ .reg .u64 t; cvta.to.shared.u64 t, %1; cvt.u32.u64 %0, t; }"
        : "=r"(a) : "l"(p));
    return a;
}
__device__ __forceinline__ void cp_async16(uint32_t sa, const void* g, int ssz) {
    asm volatile("cp.async.ca.shared.global [%0], [%1], 16, %2;"
                 :: "r"(sa), "l"(g), "r"(ssz) : "memory");
}
__device__ __forceinline__ void cp_commit() {
    asm volatile("cp.async.commit_group;" ::: "memory");
}
template <int NG>
__device__ __forceinline__ void cp_wait() {
    asm volatile("cp.async.wait_group %0;" :: "n"(NG) : "memory");
}
__device__ __forceinline__ void ldm4(uint32_t* r, uint32_t a) {
    asm volatile("ldmatrix.sync.aligned.m8n8.x4.shared.b16 {%0,%1,%2,%3}, [%4];"
                 : "=r"(r[0]), "=r"(r[1]), "=r"(r[2]), "=r"(r[3]) : "r"(a));
}
__device__ __forceinline__ void ldm2(uint32_t* r, uint32_t a) {
    asm volatile("ldmatrix.sync.aligned.m8n8.x2.shared.b16 {%0,%1}, [%2];"
                 : "=r"(r[0]), "=r"(r[1]) : "r"(a));
}
__device__ __forceinline__ void mma16816(float* c, const uint32_t* a,
                                         const uint32_t* b) {
    asm volatile(
        "mma.sync.aligned.m16n8k16.row.col.f32.bf16.bf16.f32 "
        "{%0,%1,%2,%3}, {%4,%5,%6,%7}, {%8,%9}, {%0,%1,%2,%3};"
        : "+f"(c[0]), "+f"(c[1]), "+f"(c[2]), "+f"(c[3])
        : "r"(a[0]), "r"(a[1]), "r"(a[2]), "r"(a[3]), "r"(b[0]), "r"(b[1]));
}

__device__ __forceinline__ void split_bf(float v, __nv_bfloat16& h, __nv_bfloat16& l) {
    h = __float2bfloat16(v);
    l = __float2bfloat16(v - __bfloat162float(h));
}

// ------------------------------ reductions ---------------------------------
__device__ __forceinline__ float warpReduceSum(float v) {
    #pragma unroll
    for (int o = 16; o > 0; o >>= 1) v += __shfl_xor_sync(0xffffffffu, v, o);
    return v;
}
__device__ __forceinline__ float warpReduceMax(float v) {
    #pragma unroll
    for (int o = 16; o > 0; o >>= 1) v = fmaxf(v, __shfl_xor_sync(0xffffffffu, v, o));
    return v;
}

// ------------------------------ layernorm -> bf16 hi/lo --------------------
__global__ __launch_bounds__(256) void layernorm_kernel(
    const float* __restrict__ x, const float* __restrict__ gamma,
    const float* __restrict__ beta,
    __nv_bfloat16* __restrict__ yh, __nv_bfloat16* __restrict__ yl)
{
    long long row = blockIdx.x;
    const float* xr = x + row * EDIM;

    float s = 0.f, s2 = 0.f;
    for (int i = threadIdx.x; i < EDIM; i += 256) {
        float v = xr[i];
        s += v; s2 += v * v;
    }
    __shared__ float sh[64];
    s  = warpReduceSum(s);
    s2 = warpReduceSum(s2);
    int w = threadIdx.x >> 5, l = threadIdx.x & 31;
    if (l == 0) { sh[w] = s; sh[32 + w] = s2; }
    __syncthreads();
    if (w == 0) {
        float a = (l < 8) ? sh[l] : 0.f;
        float b = (l < 8) ? sh[32 + l] : 0.f;
        a = warpReduceSum(a);
        b = warpReduceSum(b);
        if (l == 0) { sh[0] = a; sh[1] = b; }
    }
    __syncthreads();
    float mean = sh[0] * (1.0f / EDIM);
    float var  = sh[1] * (1.0f / EDIM) - mean * mean;
    float inv  = rsqrtf(var + 1e-5f);
    for (int i = threadIdx.x; i < EDIM; i += 256) {
        float v = (xr[i] - mean) * inv * gamma[i] + beta[i];
        __nv_bfloat16 h, lo; split_bf(v, h, lo);
        yh[row * EDIM + i] = h;
        yl[row * EDIM + i] = lo;
    }
}

// ------------------------------ twiddles -----------------------------------
__global__ void fill_twiddle_kernel(float2* __restrict__ tw)
{
    int k = blockIdx.x * 256 + threadIdx.x;
    if (k < 1024) {
        double ang = -6.283185307179586476925286766559 * (double)k / 2048.0;
        tw[k] = make_float2((float)cos(ang), (float)sin(ang));
    }
}

// ------------------------- transpose + split -------------------------------
__global__ __launch_bounds__(256) void transpose_split_kernel(
    const float* __restrict__ src, int R, int C,
    __nv_bfloat16* __restrict__ dh, __nv_bfloat16* __restrict__ dl, int dld)
{
    __shared__ float t[32][33];
    int c0 = blockIdx.x * 32, r0 = blockIdx.y * 32;
    int tx = threadIdx.x & 31, ty = threadIdx.x >> 5;
    for (int j = ty; j < 32; j += 8) {
        int y = r0 + j, xx = c0 + tx;
        t[j][tx] = (y < R && xx < C) ? src[(long long)y * C + xx] : 0.f;
    }
    __syncthreads();
    for (int j = ty; j < 32; j += 8) {
        int dr = c0 + j;
        int dc = r0 + tx;
        if (dr < C && dc < R) {
            __nv_bfloat16 h, lo; split_bf(t[tx][j], h, lo);
            dh[(long long)dr * dld + dc] = h;
            dl[(long long)dr * dld + dc] = lo;
        }
    }
}

// ------------------------- elementwise split -------------------------------
__global__ __launch_bounds__(256) void split1_kernel(
    const float* __restrict__ src, long long n,
    __nv_bfloat16* __restrict__ h, __nv_bfloat16* __restrict__ l)
{
    long long i = (long long)blockIdx.x * 256 + threadIdx.x;
    if (i >= n) return;
    __nv_bfloat16 hh, ll; split_bf(src[i], hh, ll);
    h[i] = hh; l[i] = ll;
}

// ------------------------- split qkv_f into fp32 qa/ka/va ------------------
__global__ __launch_bounds__(256) void split3f_kernel(
    const float* __restrict__ qkvf,
    float* __restrict__ qa, float* __restrict__ ka, float* __restrict__ va)
{
    int c = blockIdx.x * 256 + threadIdx.x;
    if (c >= N3R) return;
    long long r = blockIdx.y;
    float v = qkvf[r * N3R + c];
    int b = (c >= 650) ? 2 : (c >= 325 ? 1 : 0);
    int cc = c - b * 325;
    float* d = (b == 0) ? qa : (b == 1 ? ka : va);
    d[r * RANKP + cc] = v;
}

// ------------------------------ column FFT ---------------------------------
// 4 adjacent real cols per block of a (SEQ x ncols) per-batch matrix.
// OMODE 0: row layout out. OMODE 1: transposed out (ncols x SEQ per batch).
template <int OMODE>
__global__ __launch_bounds__(256) void fft_cols_kernel(
    const float* __restrict__ in, int ncols,
    __nv_bfloat16* __restrict__ oh, __nv_bfloat16* __restrict__ ol,
    const float2* __restrict__ tw, float scale)
{
    __shared__ float2 z1[SEQ];
    __shared__ float2 z2[SEQ];
    __shared__ float2 twz[1024];

    int col0 = blockIdx.x * 4;
    long long b = blockIdx.y;
    const float* src = in + b * (long long)SEQ * ncols + col0;
    int tid = threadIdx.x;

    for (int i = tid; i < 1024; i += 256) twz[i] = tw[i];

    for (int r = tid; r < SEQ; r += 256) {
        float4 v = *reinterpret_cast<const float4*>(src + (long long)r * ncols);
        int br = __brev((unsigned)r) >> 21;
        z1[br] = make_float2(v.x, v.y);
        z2[br] = make_float2(v.z, v.w);
    }
    __syncthreads();

    for (int s = 0; s < 11; s++) {
        int half = 1 << s;
        for (int bb = tid; bb < 1024; bb += 256) {
            int pos = bb & (half - 1);
            int i0 = ((bb >> s) << (s + 1)) + pos;
            int i1 = i0 + half;
            float2 w = twz[pos << (10 - s)];
            float2 a, c; float tr, ti;
            a = z1[i0]; c = z1[i1];
            tr = w.x * c.x - w.y * c.y;
            ti = w.x * c.y + w.y * c.x;
            z1[i0] = make_float2(a.x + tr, a.y + ti);
            z1[i1] = make_float2(a.x - tr, a.y - ti);
            a = z2[i0]; c = z2[i1];
            tr = w.x * c.x - w.y * c.y;
            ti = w.x * c.y + w.y * c.x;
            z2[i0] = make_float2(a.x + tr, a.y + ti);
            z2[i1] = make_float2(a.x - tr, a.y - ti);
        }
        __syncthreads();
    }

    float h = 0.5f * scale;
    for (int r = tid; r < SEQ; r += 256) {
        int rr = (SEQ - r) & (SEQ - 1);
        float o0 = h * (z1[r].x + z1[rr].x);
        float o1 = h * (z1[r].y + z1[rr].y);
        float o2 = h * (z2[r].x + z2[rr].x);
        float o3 = h * (z2[r].y + z2[rr].y);
        __nv_bfloat16 h0,l0,h1,l1,h2,l2,h3,l3;
        split_bf(o0,h0,l0); split_bf(o1,h1,l1);
        split_bf(o2,h2,l2); split_bf(o3,h3,l3);
        if (OMODE == 0) {
            long long off = b * (long long)SEQ * ncols + (long long)r * ncols + col0;
            oh[off+0]=h0; oh[off+1]=h1; oh[off+2]=h2; oh[off+3]=h3;
            ol[off+0]=l0; ol[off+1]=l1; ol[off+2]=l2; ol[off+3]=l3;
        } else {
            long long ob = b * (long long)ncols * SEQ;
            oh[ob + (long long)(col0+0)*SEQ + r] = h0;
            oh[ob + (long long)(col0+1)*SEQ + r] = h1;
            oh[ob + (long long)(col0+2)*SEQ + r] = h2;
            oh[ob + (long long)(col0+3)*SEQ + r] = h3;
            ol[ob + (long long)(col0+0)*SEQ + r] = l0;
            ol[ob + (long long)(col0+1)*SEQ + r] = l1;
            ol[ob + (long long)(col0+2)*SEQ + r] = l2;
            ol[ob + (long long)(col0+3)*SEQ + r] = l3;
        }
    }
}

// ------------------------------ abs-softmax -> bf16 hi/lo ------------------
__global__ __launch_bounds__(256) void softmax_abs_kernel(
    const float* __restrict__ s,
    __nv_bfloat16* __restrict__ ah, __nv_bfloat16* __restrict__ al)
{
    long long row = blockIdx.x;
    const float* sr = s + row * (long long)SEQ;
    float vals[8];
    float mx = -1e30f;
    #pragma unroll
    for (int i = 0; i < 8; i++) {
        float v = fabsf(sr[threadIdx.x + i * 256]);
        vals[i] = v;
        mx = fmaxf(mx, v);
    }
    __shared__ float sh[32];
    mx = warpReduceMax(mx);
    int w = threadIdx.x >> 5, l = threadIdx.x & 31;
    if (l == 0) sh[w] = mx;
    __syncthreads();
    if (w == 0) {
        float a = (l < 8) ? sh[l] : -1e30f;
        a = warpReduceMax(a);
        if (l == 0) sh[0] = a;
    }
    __syncthreads();
    float M = sh[0];
    float sum = 0.f;
    #pragma unroll
    for (int i = 0; i < 8; i++) {
        vals[i] = expf(vals[i] - M);
        sum += vals[i];
    }
    __syncthreads();
    sum = warpReduceSum(sum);
    if (l == 0) sh[w] = sum;
    __syncthreads();
    if (w == 0) {
        float a = (l < 8) ? sh[l] : 0.f;
        a = warpReduceSum(a);
        if (l == 0) sh[0] = a;
    }
    __syncthreads();
    float inv = 1.0f / sh[0];
    #pragma unroll
    for (int i = 0; i < 8; i++) {
        float v = vals[i] * inv;
        __nv_bfloat16 h, lo; split_bf(v, h, lo);
        long long off = row * (long long)SEQ + threadIdx.x + i * 256;
        ah[off] = h;
        al[off] = lo;
    }
}

// ------------------------------ HMMA GEMM ----------------------------------
// C[M,N] = alpha * (Ah+Al)[M,K] @ (Bh+Bl)[N,K]^T (+ Res), lo*lo dropped.
// 128x128 CTA tile, BK=32, 8 warps (2x4), warp tile 64x32, 3-stage cp.async,
// pass-major MMA order. M and N fully guarded (ragged tiles OK).
#define BKC     32
#define ROWB    80
#define T_TB    (128 * ROWB)
#define STAGEB  (4 * T_TB)
#define GEMM_SMEM (3 * STAGEB)   // 122880

__device__ __forceinline__ void load_tile_async(
    uint32_t tb, const __nv_bfloat16* __restrict__ src, long long row0,
    int ld, int nvalid, int kbase, int K, int tid)
{
    #pragma unroll
    for (int j = 0; j < 2; j++) {
        int row = (tid >> 2) + j * 64;
        int c = tid & 3;
        uint32_t sa = tb + row * ROWB + c * 16;
        const __nv_bfloat16* g = src + (row0 + row) * (long long)ld + kbase + c * 8;
        int ssz = (row < nvalid && (kbase + c * 8) < K) ? 16 : 0;
        cp_async16(sa, g, ssz);
    }
}

__device__ __forceinline__ void load_stage(
    uint32_t tb,
    const __nv_bfloat16* Ah, const __nv_bfloat16* Al, long long m0, int lda,
    int nvA,
    const __nv_bfloat16* Bh, const __nv_bfloat16* Bl, int n0, int ldb,
    int nvB, int kb, int K, int tid)
{
    load_tile_async(tb,            Ah, m0, lda, nvA, kb, K, tid);
    load_tile_async(tb + T_TB,     Al, m0, lda, nvA, kb, K, tid);
    load_tile_async(tb + 2 * T_TB, Bh, n0, ldb, nvB, kb, K, tid);
    load_tile_async(tb + 3 * T_TB, Bl, n0, ldb, nvB, kb, K, tid);
}

__global__ void __launch_bounds__(256, 1) hmma_gemm_kernel(
    const __nv_bfloat16* __restrict__ Ah, const __nv_bfloat16* __restrict__ Al,
    int lda, long long sA,
    const __nv_bfloat16* __restrict__ Bh, const __nv_bfloat16* __restrict__ Bl,
    int ldb, long long sB,
    float* __restrict__ C, int ldc, long long sC,
    int M, int N, int K, float alpha,
    const float* __restrict__ Res, long long sRes)
{
    extern __shared__ char smem[];
    uint32_t sb = smem_u32(smem);
    int tid = threadIdx.x;
    int lane = tid & 31, w = tid >> 5;
    int wm = w & 1, wn = w >> 1;

    long long bz = blockIdx.z;
    Ah += bz * sA; Al += bz * sA;
    Bh += bz * sB; Bl += bz * sB;
    C  += bz * sC;
    if (Res) Res += bz * sRes;

    long long m0 = (long long)blockIdx.y * 128;
    int n0 = blockIdx.x * 128;
    int nvA = M - (int)m0; if (nvA > 128) nvA = 128;
    int nvB = N - n0; if (nvB > 128) nvB = 128;

    float acc[4][4][4];
    #pragma unroll
    for (int i = 0; i < 4; i++)
        #pragma unroll
        for (int j = 0; j < 4; j++)
            #pragma unroll
            for (int e = 0; e < 4; e++) acc[i][j][e] = 0.f;

    int l16 = lane & 15;
    uint32_t offA = (uint32_t)((wm * 64 + l16) * ROWB + ((lane >> 4) & 1) * 16);
    uint32_t offB = (uint32_t)((wn * 32 + (l16 & 7)) * ROWB + ((l16 >> 3) & 1) * 16);

    int nch = (K + BKC - 1) / BKC;

    load_stage(sb, Ah, Al, m0, lda, nvA, Bh, Bl, n0, ldb, nvB, 0, K, tid);
    cp_commit();
    if (nch > 1) {
        load_stage(sb + STAGEB, Ah, Al, m0, lda, nvA, Bh, Bl, n0, ldb, nvB,
                   BKC, K, tid);
    }
    cp_commit();

    int st = 0;
    for (int kt = 0; kt < nch; kt++) {
        if (kt + 2 < nch) {
            int st2 = st + 2; if (st2 >= 3) st2 -= 3;
            load_stage(sb + st2 * STAGEB, Ah, Al, m0, lda, nvA, Bh, Bl, n0,
                       ldb, nvB, (kt + 2) * BKC, K, tid);
            cp_commit();
            cp_wait<2>();
        } else if (kt + 1 < nch) {
            cp_wait<1>();
        } else {
            cp_wait<0>();
        }
        __syncthreads();

        uint32_t tb = sb + st * STAGEB;
        #pragma unroll
        for (int ks = 0; ks < 2; ks++) {
            uint32_t kf = (uint32_t)(ks * 32);
            uint32_t arH[4][4], arL[4][4], brH[4][2], brL[4][2];
            #pragma unroll
            for (int mi = 0; mi < 4; mi++) {
                uint32_t a = tb + offA + (uint32_t)(mi * 16 * ROWB) + kf;
                ldm4(arH[mi], a);
                ldm4(arL[mi], a + T_TB);
            }
            #pragma unroll
            for (int ni = 0; ni < 4; ni++) {
                uint32_t a = tb + 2 * T_TB + offB + (uint32_t)(ni * 8 * ROWB) + kf;
                ldm2(brH[ni], a);
                ldm2(brL[ni], a + T_TB);
            }
            #pragma unroll
            for (int mi = 0; mi < 4; mi++)
                #pragma unroll
                for (int ni = 0; ni < 4; ni++)
                    mma16816(acc[mi][ni], arH[mi], brH[ni]);
            #pragma unroll
            for (int mi = 0; mi < 4; mi++)
                #pragma unroll
                for (int ni = 0; ni < 4; ni++)
                    mma16816(acc[mi][ni], arH[mi], brL[ni]);
            #pragma unroll
            for (int mi = 0; mi < 4; mi++)
                #pragma unroll
                for (int ni = 0; ni < 4; ni++)
                    mma16816(acc[mi][ni], arL[mi], brH[ni]);
        }
        __syncthreads();
        st++; if (st >= 3) st = 0;
    }

    // epilogue (row + col guarded)
    #pragma unroll
    for (int mi = 0; mi < 4; mi++) {
        long long r0 = m0 + wm * 64 + mi * 16 + (lane >> 2);
        bool vr0 = r0 < M, vr1 = (r0 + 8) < M;
        #pragma unroll
        for (int ni = 0; ni < 4; ni++) {
            int col = n0 + wn * 32 + ni * 8 + (lane & 3) * 2;
            float* a = acc[mi][ni];
            if (col < N) {
                long long o0 = r0 * (long long)ldc + col;
                long long o1 = (r0 + 8) * (long long)ldc + col;
                bool vc1 = (col + 1) < N;
                if (vr0) {
                    float v0 = alpha * a[0];
                    if (Res) v0 += Res[o0];
                    C[o0] = v0;
                    if (vc1) {
                        float v1 = alpha * a[1];
                        if (Res) v1 += Res[o0 + 1];
                        C[o0 + 1] = v1;
                    }
                }
                if (vr1) {
                    float v2 = alpha * a[2];
                    if (Res) v2 += Res[o1];
                    C[o1] = v2;
                    if (vc1) {
                        float v3 = alpha * a[3];
                        if (Res) v3 += Res[o1 + 1];
                        C[o1 + 1] = v3;
                    }
                }
            }
        }
    }
}

// ------------------------------ host side ----------------------------------
static inline void run_mma(const __nv_bfloat16* Ah, const __nv_bfloat16* Al,
                           int lda, long long sA,
                           const __nv_bfloat16* Bh, const __nv_bfloat16* Bl,
                           int ldb, long long sB,
                           float* C, int ldc, long long sC,
                           int M, int N, int K, float alpha,
                           const float* Res, long long sRes, int nb)
{
    dim3 grid((N + 127) / 128, (M + 127) / 128, nb);
    hmma_gemm_kernel<<<grid, 256, GEMM_SMEM>>>(Ah, Al, lda, sA, Bh, Bl, ldb, sB,
                                               C, ldc, sC, M, N, K, alpha,
                                               Res, sRes);
}

extern "C" void kernel_launch(void* const* d_in, const int* in_sizes, int n_in,
                              void* d_out, int out_size)
{
    const float* x     = (const float*)d_in[0];  // (4,2048,1280)
    const float* Wqkv  = (const float*)d_in[1];  // (1280,975)
    const float* Wq    = (const float*)d_in[2];  // (325,1280)
    const float* Wk    = (const float*)d_in[3];  // (325,1280)
    const float* Wv    = (const float*)d_in[4];  // (325,1280)
    const float* Wout  = (const float*)d_in[5];  // (1280,1280)
    const float* gamma = (const float*)d_in[6];
    const float* beta  = (const float*)d_in[7];
    float* out = (float*)d_out;                  // (4,2048,1280)

    static int smem_set = 0;
    if (!smem_set) {
        cudaFuncSetAttribute(hmma_gemm_kernel,
                             cudaFuncAttributeMaxDynamicSharedMemorySize,
                             GEMM_SMEM);
        smem_set = 1;
    }

    float* fb = nullptr;
    __nv_bfloat16* hb = nullptr;
    cudaGetSymbolAddress((void**)&fb, g_buf);
    cudaGetSymbolAddress((void**)&hb, g_hb);

    float*  scores = fb + F_SC;
    float*  qa     = fb + F_QA;
    float*  ka     = fb + F_KA;
    float*  va     = fb + F_VA;
    float*  sM_f   = fb + F_SM;
    float*  y_f    = fb + F_Y;
    float*  mqk_f  = fb + F_MQK;
    float*  wvo_f  = fb + F_WVO;
    float2* tw     = (float2*)(fb + F_TW);

    const long long sR = (long long)SEQ * RANKP;   // 2048*328 per batch
    const long long sS = (long long)SEQ * SEQ;
    const float scale = 0.07905694150420949f;      // 1/sqrt(160)

    // 1. LayerNorm; twiddles; weight prep
    layernorm_kernel<<<BSROWS, 256>>>(x, gamma, beta, hb + H_XNH, hb + H_XNL);
    fill_twiddle_kernel<<<4, 256>>>(tw);
    transpose_split_kernel<<<dim3(31, 40), 256>>>(
        Wqkv, 1280, 975, hb + H_WQKVH, hb + H_WQKVL, 1280);
    split1_kernel<<<(416000 + 255) / 256, 256>>>(Wq, 416000LL,
                                                 hb + H_WQSH, hb + H_WQSL);
    split1_kernel<<<(416000 + 255) / 256, 256>>>(Wk, 416000LL,
                                                 hb + H_WKSH, hb + H_WKSL);
    split1_kernel<<<(416000 + 255) / 256, 256>>>(Wv, 416000LL,
                                                 hb + H_WVSH, hb + H_WVSL);
    transpose_split_kernel<<<dim3(40, 40), 256>>>(
        Wout, 1280, 1280, hb + H_WOTH, hb + H_WOTL, 1280);

    // 2. Precompute Mqk = Wq @ Wk^T (325x325), Wvo = Wv @ Wout (325x1280)
    run_mma(hb + H_WQSH, hb + H_WQSL, 1280, 0,
            hb + H_WKSH, hb + H_WKSL, 1280, 0,
            mqk_f, 325, 0, 325, 325, 1280, 1.f, nullptr, 0, 1);
    run_mma(hb + H_WVSH, hb + H_WVSL, 1280, 0,
            hb + H_WOTH, hb + H_WOTL, 1280, 0,
            wvo_f, 1280, 0, 325, 1280, 1280, 1.f, nullptr, 0, 1);
    transpose_split_kernel<<<dim3(11, 11), 256>>>(
        mqk_f, 325, 325, hb + H_MQKTH, hb + H_MQKTL, RANKP);
    transpose_split_kernel<<<dim3(40, 11), 256>>>(
        wvo_f, 325, 1280, hb + H_WVOTH, hb + H_WVOTL, RANKP);

    // 3. qkv_f = xn @ Wqkv  (8192 x 975)
    run_mma(hb + H_XNH, hb + H_XNL, EDIM, 0,
            hb + H_WQKVH, hb + H_WQKVL, EDIM, 0,
            scores, N3R, 0, BSROWS, N3R, EDIM, 1.f, nullptr, 0, 1);

    // 4. split into fp32 qa/ka/va (ld 328, pad cols stay zero)
    split3f_kernel<<<dim3(4, BSROWS), 256>>>(scores, qa, ka, va);

    // 5. FFT rank-space: qfa/kfa (row layout), vfaT (transposed)
    {
        dim3 g(RANKP / 4, BATCH);
        fft_cols_kernel<0><<<g, 256>>>(qa, RANKP, hb + H_QFAH, hb + H_QFAL,
                                       tw, 1.0f);
        fft_cols_kernel<0><<<g, 256>>>(ka, RANKP, hb + H_KFAH, hb + H_KFAL,
                                       tw, 1.0f);
        fft_cols_kernel<1><<<g, 256>>>(va, RANKP, hb + H_VFATH, hb + H_VFATL,
                                       tw, 1.0f);
    }

    // 6. sM = qfa @ Mqk  (8192 x 325, K=328)
    run_mma(hb + H_QFAH, hb + H_QFAL, RANKP, 0,
            hb + H_MQKTH, hb + H_MQKTL, RANKP, 0,
            sM_f, RANKP, 0, BSROWS, RANKD, RANKP, 1.f, nullptr, 0, 1);
    split1_kernel<<<(unsigned)((8192LL * RANKP + 255) / 256), 256>>>(
        sM_f, 8192LL * RANKP, hb + H_SMH, hb + H_SML);

    // 7. scores = sM @ kfa^T / sqrt(160)  (per batch 2048x2048, K=328)
    run_mma(hb + H_SMH, hb + H_SML, RANKP, sR,
            hb + H_KFAH, hb + H_KFAL, RANKP, sR,
            scores, SEQ, sS, SEQ, SEQ, RANKP, scale, nullptr, 0, BATCH);

    // 8. attn = softmax(|scores|) -> bf16 hi/lo
    softmax_abs_kernel<<<BATCH * SEQ, 256>>>(scores, hb + H_ATH, hb + H_ATL);

    // 9. y = attn @ vfa  (per batch 2048 x 325, K=2048)
    run_mma(hb + H_ATH, hb + H_ATL, SEQ, sS,
            hb + H_VFATH, hb + H_VFATL, SEQ, sR,
            y_f, RANKP, sR, SEQ, RANKD, SEQ, 1.f, nullptr, 0, BATCH);

    // 10. z = Re(IFFT(y)) = Re(FFT(y))/2048 -> bf16 hi/lo
    {
        dim3 g(RANKP / 4, BATCH);
        fft_cols_kernel<0><<<g, 256>>>(y_f, RANKP, hb + H_ZH, hb + H_ZL,
                                       tw, 1.0f / 2048.0f);
    }

    // 11. out = x + z @ Wvo  (8192 x 1280, K=328)
    run_mma(hb + H_ZH, hb + H_ZL, RANKP, 0,
            hb + H_WVOTH, hb + H_WVOTL, RANKP, 0,
            out, EDIM, 0, BSROWS, EDIM, RANKP, 1.f, x, 0, 1);
}

// round 13
// speedup vs baseline: 2.5843x; 1.1380x over previous
#include <cuda_runtime.h>
#include <cuda_bf16.h>
#include <math.h>
#include <stdint.h>

// ---------------------------------------------------------------------------
// RobustAttentionBlock (B=4, S=2048, E=1280, R=325) — rank-factored version
//
// scores = FFT(qa)·(Wq Wk^T)·FFT(ka)^T / sqrt(160)
// out    = x + IFFT(attn·FFT(va)) · (Wv·W_out)
// Score path: exact bf16 2-way split (3 mma passes). Post-softmax path
// (attn@vfa, z@Wvo): single-pass bf16 — proj is only ~8% of output norm,
// so 0.3% relative error there lands ~2.5e-4 on the final output.
// ---------------------------------------------------------------------------

#define EDIM   1280
#define SEQ    2048
#define BATCH  4
#define RANKD  325
#define RANKP  328
#define N3R    975
#define BSROWS (BATCH * SEQ)

// ------------------------- fp32 scratch ------------------------------------
#define F_SC   0LL                                  // scores / qkv_f temp
#define F_QA   (F_SC  + 4LL*2048*2048)
#define F_KA   (F_QA  + 8192LL*RANKP)
#define F_VA   (F_KA  + 8192LL*RANKP)
#define F_Y    (F_VA  + 8192LL*RANKP)               // 4 x 2048 x 328
#define F_MQK  (F_Y   + 8192LL*RANKP)               // 325 x 325
#define F_WVO  (F_MQK + 105632LL)                   // 325 x 1280
#define F_TW   (F_WVO + 416000LL)
#define F_TOT  (F_TW  + 2048LL)
__device__ float g_buf[F_TOT];

// ------------------------- bf16 scratch ------------------------------------
#define SZ_T    (8192LL*1280)
#define SZ_R    (8192LL*RANKP)
#define SZ_SC   (4LL*2048*2048)
#define H_XNH    0LL
#define H_XNL    (H_XNH   + SZ_T)
#define H_WQKVH  (H_XNL   + SZ_T)
#define H_WQKVL  (H_WQKVH + 975LL*1280)
#define H_WQSH   (H_WQKVL + 975LL*1280)
#define H_WQSL   (H_WQSH  + 416000LL)
#define H_WKSH   (H_WQSL  + 416000LL)
#define H_WKSL   (H_WKSH  + 416000LL)
#define H_WVSH   (H_WKSL  + 416000LL)
#define H_WVSL   (H_WVSH  + 416000LL)
#define H_WOTH   (H_WVSL  + 416000LL)
#define H_WOTL   (H_WOTH  + 1280LL*1280)
#define H_MQKTH  (H_WOTL  + 1280LL*1280)
#define H_MQKTL  (H_MQKTH + 325LL*RANKP)
#define H_WVOTH  (H_MQKTL + 325LL*RANKP)
#define H_WVOTL  (H_WVOTH + 1280LL*RANKP)
#define H_QFAH   (H_WVOTL + 1280LL*RANKP)
#define H_QFAL   (H_QFAH  + SZ_R)
#define H_KFAH   (H_QFAL  + SZ_R)
#define H_KFAL   (H_KFAH  + SZ_R)
#define H_VFATH  (H_KFAL  + SZ_R)    // per batch: 328 x 2048 (hi only used)
#define H_SMH    (H_VFATH + SZ_R)
#define H_SML    (H_SMH   + SZ_R)
#define H_ATH    (H_SML   + SZ_R)    // attn hi only
#define H_ZH     (H_ATH   + SZ_SC)
#define H_TOT    (H_ZH    + SZ_R)
__device__ __nv_bfloat16 g_hb[H_TOT];

// ------------------------------ PTX helpers --------------------------------
__device__ __forceinline__ uint32_t smem_u32(const void* p) {
    uint32_t a;
    asm("{ .reg .u64 t; cvta.to.shared.u64 t, %1; cvt.u32.u64 %0, t; }"
        : "=r"(a) : "l"(p));
    return a;
}
__device__ __forceinline__ void cp_async16(uint32_t sa, const void* g, int ssz) {
    asm volatile("cp.async.ca.shared.global [%0], [%1], 16, %2;"
                 :: "r"(sa), "l"(g), "r"(ssz) : "memory");
}
__device__ __forceinline__ void cp_commit() {
    asm volatile("cp.async.commit_group;" ::: "memory");
}
template <int NG>
__device__ __forceinline__ void cp_wait() {
    asm volatile("cp.async.wait_group %0;" :: "n"(NG) : "memory");
}
__device__ __forceinline__ void ldm4(uint32_t* r, uint32_t a) {
    asm volatile("ldmatrix.sync.aligned.m8n8.x4.shared.b16 {%0,%1,%2,%3}, [%4];"
                 : "=r"(r[0]), "=r"(r[1]), "=r"(r[2]), "=r"(r[3]) : "r"(a));
}
__device__ __forceinline__ void ldm2(uint32_t* r, uint32_t a) {
    asm volatile("ldmatrix.sync.aligned.m8n8.x2.shared.b16 {%0,%1}, [%2];"
                 : "=r"(r[0]), "=r"(r[1]) : "r"(a));
}
__device__ __forceinline__ void mma16816(float* c, const uint32_t* a,
                                         const uint32_t* b) {
    asm volatile(
        "mma.sync.aligned.m16n8k16.row.col.f32.bf16.bf16.f32 "
        "{%0,%1,%2,%3}, {%4,%5,%6,%7}, {%8,%9}, {%0,%1,%2,%3};"
        : "+f"(c[0]), "+f"(c[1]), "+f"(c[2]), "+f"(c[3])
        : "r"(a[0]), "r"(a[1]), "r"(a[2]), "r"(a[3]), "r"(b[0]), "r"(b[1]));
}

__device__ __forceinline__ void split_bf(float v, __nv_bfloat16& h, __nv_bfloat16& l) {
    h = __float2bfloat16(v);
    l = __float2bfloat16(v - __bfloat162float(h));
}

// ------------------------------ reductions ---------------------------------
__device__ __forceinline__ float warpReduceSum(float v) {
    #pragma unroll
    for (int o = 16; o > 0; o >>= 1) v += __shfl_xor_sync(0xffffffffu, v, o);
    return v;
}
__device__ __forceinline__ float warpReduceMax(float v) {
    #pragma unroll
    for (int o = 16; o > 0; o >>= 1) v = fmaxf(v, __shfl_xor_sync(0xffffffffu, v, o));
    return v;
}

// ------------------------------ layernorm -> bf16 hi/lo --------------------
__global__ __launch_bounds__(256) void layernorm_kernel(
    const float* __restrict__ x, const float* __restrict__ gamma,
    const float* __restrict__ beta,
    __nv_bfloat16* __restrict__ yh, __nv_bfloat16* __restrict__ yl)
{
    long long row = blockIdx.x;
    const float* xr = x + row * EDIM;

    float s = 0.f, s2 = 0.f;
    for (int i = threadIdx.x; i < EDIM; i += 256) {
        float v = xr[i];
        s += v; s2 += v * v;
    }
    __shared__ float sh[64];
    s  = warpReduceSum(s);
    s2 = warpReduceSum(s2);
    int w = threadIdx.x >> 5, l = threadIdx.x & 31;
    if (l == 0) { sh[w] = s; sh[32 + w] = s2; }
    __syncthreads();
    if (w == 0) {
        float a = (l < 8) ? sh[l] : 0.f;
        float b = (l < 8) ? sh[32 + l] : 0.f;
        a = warpReduceSum(a);
        b = warpReduceSum(b);
        if (l == 0) { sh[0] = a; sh[1] = b; }
    }
    __syncthreads();
    float mean = sh[0] * (1.0f / EDIM);
    float var  = sh[1] * (1.0f / EDIM) - mean * mean;
    float inv  = rsqrtf(var + 1e-5f);
    for (int i = threadIdx.x; i < EDIM; i += 256) {
        float v = (xr[i] - mean) * inv * gamma[i] + beta[i];
        __nv_bfloat16 h, lo; split_bf(v, h, lo);
        yh[row * EDIM + i] = h;
        yl[row * EDIM + i] = lo;
    }
}

// ------------------------------ twiddles -----------------------------------
__global__ void fill_twiddle_kernel(float2* __restrict__ tw)
{
    int k = blockIdx.x * 256 + threadIdx.x;
    if (k < 1024) {
        double ang = -6.283185307179586476925286766559 * (double)k / 2048.0;
        tw[k] = make_float2((float)cos(ang), (float)sin(ang));
    }
}

// ------------------------- transpose + split -------------------------------
__global__ __launch_bounds__(256) void transpose_split_kernel(
    const float* __restrict__ src, int R, int C,
    __nv_bfloat16* __restrict__ dh, __nv_bfloat16* __restrict__ dl, int dld)
{
    __shared__ float t[32][33];
    int c0 = blockIdx.x * 32, r0 = blockIdx.y * 32;
    int tx = threadIdx.x & 31, ty = threadIdx.x >> 5;
    for (int j = ty; j < 32; j += 8) {
        int y = r0 + j, xx = c0 + tx;
        t[j][tx] = (y < R && xx < C) ? src[(long long)y * C + xx] : 0.f;
    }
    __syncthreads();
    for (int j = ty; j < 32; j += 8) {
        int dr = c0 + j;
        int dc = r0 + tx;
        if (dr < C && dc < R) {
            __nv_bfloat16 h, lo; split_bf(t[tx][j], h, lo);
            dh[(long long)dr * dld + dc] = h;
            dl[(long long)dr * dld + dc] = lo;
        }
    }
}

// ------------------------- elementwise split -------------------------------
__global__ __launch_bounds__(256) void split1_kernel(
    const float* __restrict__ src, long long n,
    __nv_bfloat16* __restrict__ h, __nv_bfloat16* __restrict__ l)
{
    long long i = (long long)blockIdx.x * 256 + threadIdx.x;
    if (i >= n) return;
    __nv_bfloat16 hh, ll; split_bf(src[i], hh, ll);
    h[i] = hh; l[i] = ll;
}

// ------------------------- split qkv_f into fp32 qa/ka/va ------------------
__global__ __launch_bounds__(256) void split3f_kernel(
    const float* __restrict__ qkvf,
    float* __restrict__ qa, float* __restrict__ ka, float* __restrict__ va)
{
    int c = blockIdx.x * 256 + threadIdx.x;
    if (c >= N3R) return;
    long long r = blockIdx.y;
    float v = qkvf[r * N3R + c];
    int b = (c >= 650) ? 2 : (c >= 325 ? 1 : 0);
    int cc = c - b * 325;
    float* d = (b == 0) ? qa : (b == 1 ? ka : va);
    d[r * RANKP + cc] = v;
}

// ------------------------------ column FFT ---------------------------------
// OMODE 0: row layout out. OMODE 1: transposed out. WLO: write lo plane.
template <int OMODE, int WLO>
__global__ __launch_bounds__(256) void fft_cols_kernel(
    const float* __restrict__ in, int ncols,
    __nv_bfloat16* __restrict__ oh, __nv_bfloat16* __restrict__ ol,
    const float2* __restrict__ tw, float scale)
{
    __shared__ float2 z1[SEQ];
    __shared__ float2 z2[SEQ];
    __shared__ float2 twz[1024];

    int col0 = blockIdx.x * 4;
    long long b = blockIdx.y;
    const float* src = in + b * (long long)SEQ * ncols + col0;
    int tid = threadIdx.x;

    for (int i = tid; i < 1024; i += 256) twz[i] = tw[i];

    for (int r = tid; r < SEQ; r += 256) {
        float4 v = *reinterpret_cast<const float4*>(src + (long long)r * ncols);
        int br = __brev((unsigned)r) >> 21;
        z1[br] = make_float2(v.x, v.y);
        z2[br] = make_float2(v.z, v.w);
    }
    __syncthreads();

    for (int s = 0; s < 11; s++) {
        int half = 1 << s;
        for (int bb = tid; bb < 1024; bb += 256) {
            int pos = bb & (half - 1);
            int i0 = ((bb >> s) << (s + 1)) + pos;
            int i1 = i0 + half;
            float2 w = twz[pos << (10 - s)];
            float2 a, c; float tr, ti;
            a = z1[i0]; c = z1[i1];
            tr = w.x * c.x - w.y * c.y;
            ti = w.x * c.y + w.y * c.x;
            z1[i0] = make_float2(a.x + tr, a.y + ti);
            z1[i1] = make_float2(a.x - tr, a.y - ti);
            a = z2[i0]; c = z2[i1];
            tr = w.x * c.x - w.y * c.y;
            ti = w.x * c.y + w.y * c.x;
            z2[i0] = make_float2(a.x + tr, a.y + ti);
            z2[i1] = make_float2(a.x - tr, a.y - ti);
        }
        __syncthreads();
    }

    float h = 0.5f * scale;
    for (int r = tid; r < SEQ; r += 256) {
        int rr = (SEQ - r) & (SEQ - 1);
        float o0 = h * (z1[r].x + z1[rr].x);
        float o1 = h * (z1[r].y + z1[rr].y);
        float o2 = h * (z2[r].x + z2[rr].x);
        float o3 = h * (z2[r].y + z2[rr].y);
        __nv_bfloat16 h0,l0,h1,l1,h2,l2,h3,l3;
        split_bf(o0,h0,l0); split_bf(o1,h1,l1);
        split_bf(o2,h2,l2); split_bf(o3,h3,l3);
        if (OMODE == 0) {
            long long off = b * (long long)SEQ * ncols + (long long)r * ncols + col0;
            oh[off+0]=h0; oh[off+1]=h1; oh[off+2]=h2; oh[off+3]=h3;
            if (WLO) {
                ol[off+0]=l0; ol[off+1]=l1; ol[off+2]=l2; ol[off+3]=l3;
            }
        } else {
            long long ob = b * (long long)ncols * SEQ;
            oh[ob + (long long)(col0+0)*SEQ + r] = h0;
            oh[ob + (long long)(col0+1)*SEQ + r] = h1;
            oh[ob + (long long)(col0+2)*SEQ + r] = h2;
            oh[ob + (long long)(col0+3)*SEQ + r] = h3;
            if (WLO) {
                ol[ob + (long long)(col0+0)*SEQ + r] = l0;
                ol[ob + (long long)(col0+1)*SEQ + r] = l1;
                ol[ob + (long long)(col0+2)*SEQ + r] = l2;
                ol[ob + (long long)(col0+3)*SEQ + r] = l3;
            }
        }
    }
}

// ------------------------------ abs-softmax -> bf16 hi ---------------------
__global__ __launch_bounds__(256) void softmax_abs_kernel(
    const float* __restrict__ s, __nv_bfloat16* __restrict__ ah)
{
    long long row = blockIdx.x;
    const float* sr = s + row * (long long)SEQ;
    float vals[8];
    float mx = -1e30f;
    #pragma unroll
    for (int i = 0; i < 8; i++) {
        float v = fabsf(sr[threadIdx.x + i * 256]);
        vals[i] = v;
        mx = fmaxf(mx, v);
    }
    __shared__ float sh[32];
    mx = warpReduceMax(mx);
    int w = threadIdx.x >> 5, l = threadIdx.x & 31;
    if (l == 0) sh[w] = mx;
    __syncthreads();
    if (w == 0) {
        float a = (l < 8) ? sh[l] : -1e30f;
        a = warpReduceMax(a);
        if (l == 0) sh[0] = a;
    }
    __syncthreads();
    float M = sh[0];
    float sum = 0.f;
    #pragma unroll
    for (int i = 0; i < 8; i++) {
        vals[i] = expf(vals[i] - M);
        sum += vals[i];
    }
    __syncthreads();
    sum = warpReduceSum(sum);
    if (l == 0) sh[w] = sum;
    __syncthreads();
    if (w == 0) {
        float a = (l < 8) ? sh[l] : 0.f;
        a = warpReduceSum(a);
        if (l == 0) sh[0] = a;
    }
    __syncthreads();
    float inv = 1.0f / sh[0];
    #pragma unroll
    for (int i = 0; i < 8; i++) {
        long long off = row * (long long)SEQ + threadIdx.x + i * 256;
        ah[off] = __float2bfloat16(vals[i] * inv);
    }
}

// ------------------------------ HMMA GEMM ----------------------------------
// SPLIT=3: C = alpha*(Ah@Bh^T + Ah@Bl^T + Al@Bh^T); SPLIT=1: C = alpha*Ah@Bh^T.
// OM=0: fp32 C (+Res). OM=1: bf16 hi/lo C (Ch, Cl).
// 128x128 CTA tile, BK=32, 8 warps (2x4), warp tile 64x32, 3-stage cp.async,
// pass-major MMA order, M/N fully guarded.
#define BKC     32
#define ROWB    80
#define T_TB    (128 * ROWB)
#define STAGEB  (4 * T_TB)
#define GEMM_SMEM (3 * STAGEB)   // 122880

__device__ __forceinline__ void load_tile_async(
    uint32_t tb, const __nv_bfloat16* __restrict__ src, long long row0,
    int ld, int nvalid, int kbase, int K, int tid)
{
    #pragma unroll
    for (int j = 0; j < 2; j++) {
        int row = (tid >> 2) + j * 64;
        int c = tid & 3;
        uint32_t sa = tb + row * ROWB + c * 16;
        const __nv_bfloat16* g = src + (row0 + row) * (long long)ld + kbase + c * 8;
        int ssz = (row < nvalid && (kbase + c * 8) < K) ? 16 : 0;
        cp_async16(sa, g, ssz);
    }
}

template <int SPLIT>
__device__ __forceinline__ void load_stage(
    uint32_t tb,
    const __nv_bfloat16* Ah, const __nv_bfloat16* Al, long long m0, int lda,
    int nvA,
    const __nv_bfloat16* Bh, const __nv_bfloat16* Bl, int n0, int ldb,
    int nvB, int kb, int K, int tid)
{
    load_tile_async(tb,            Ah, m0, lda, nvA, kb, K, tid);
    load_tile_async(tb + 2 * T_TB, Bh, n0, ldb, nvB, kb, K, tid);
    if (SPLIT == 3) {
        load_tile_async(tb + T_TB,     Al, m0, lda, nvA, kb, K, tid);
        load_tile_async(tb + 3 * T_TB, Bl, n0, ldb, nvB, kb, K, tid);
    }
}

template <int SPLIT, int OM>
__global__ void __launch_bounds__(256, 1) hmma_gemm_kernel(
    const __nv_bfloat16* __restrict__ Ah, const __nv_bfloat16* __restrict__ Al,
    int lda, long long sA,
    const __nv_bfloat16* __restrict__ Bh, const __nv_bfloat16* __restrict__ Bl,
    int ldb, long long sB,
    float* __restrict__ C, int ldc, long long sC,
    __nv_bfloat16* __restrict__ Ch, __nv_bfloat16* __restrict__ Cl,
    int M, int N, int K, float alpha,
    const float* __restrict__ Res, long long sRes)
{
    extern __shared__ char smem[];
    uint32_t sb = smem_u32(smem);
    int tid = threadIdx.x;
    int lane = tid & 31, w = tid >> 5;
    int wm = w & 1, wn = w >> 1;

    long long bz = blockIdx.z;
    Ah += bz * sA; if (SPLIT == 3) Al += bz * sA;
    Bh += bz * sB; if (SPLIT == 3) Bl += bz * sB;
    if (OM == 0) C += bz * sC; else { Ch += bz * sC; Cl += bz * sC; }
    if (Res) Res += bz * sRes;

    long long m0 = (long long)blockIdx.y * 128;
    int n0 = blockIdx.x * 128;
    int nvA = M - (int)m0; if (nvA > 128) nvA = 128;
    int nvB = N - n0; if (nvB > 128) nvB = 128;

    float acc[4][4][4];
    #pragma unroll
    for (int i = 0; i < 4; i++)
        #pragma unroll
        for (int j = 0; j < 4; j++)
            #pragma unroll
            for (int e = 0; e < 4; e++) acc[i][j][e] = 0.f;

    int l16 = lane & 15;
    uint32_t offA = (uint32_t)((wm * 64 + l16) * ROWB + ((lane >> 4) & 1) * 16);
    uint32_t offB = (uint32_t)((wn * 32 + (l16 & 7)) * ROWB + ((l16 >> 3) & 1) * 16);

    int nch = (K + BKC - 1) / BKC;

    load_stage<SPLIT>(sb, Ah, Al, m0, lda, nvA, Bh, Bl, n0, ldb, nvB, 0, K, tid);
    cp_commit();
    if (nch > 1) {
        load_stage<SPLIT>(sb + STAGEB, Ah, Al, m0, lda, nvA, Bh, Bl, n0, ldb,
                          nvB, BKC, K, tid);
    }
    cp_commit();

    int st = 0;
    for (int kt = 0; kt < nch; kt++) {
        if (kt + 2 < nch) {
            int st2 = st + 2; if (st2 >= 3) st2 -= 3;
            load_stage<SPLIT>(sb + st2 * STAGEB, Ah, Al, m0, lda, nvA, Bh, Bl,
                              n0, ldb, nvB, (kt + 2) * BKC, K, tid);
            cp_commit();
            cp_wait<2>();
        } else if (kt + 1 < nch) {
            cp_wait<1>();
        } else {
            cp_wait<0>();
        }
        __syncthreads();

        uint32_t tb = sb + st * STAGEB;
        #pragma unroll
        for (int ks = 0; ks < 2; ks++) {
            uint32_t kf = (uint32_t)(ks * 32);
            uint32_t arH[4][4], brH[4][2];
            #pragma unroll
            for (int mi = 0; mi < 4; mi++)
                ldm4(arH[mi], tb + offA + (uint32_t)(mi * 16 * ROWB) + kf);
            #pragma unroll
            for (int ni = 0; ni < 4; ni++)
                ldm2(brH[ni], tb + 2 * T_TB + offB + (uint32_t)(ni * 8 * ROWB) + kf);
            #pragma unroll
            for (int mi = 0; mi < 4; mi++)
                #pragma unroll
                for (int ni = 0; ni < 4; ni++)
                    mma16816(acc[mi][ni], arH[mi], brH[ni]);

            if (SPLIT == 3) {
                uint32_t arL[4][4], brL[4][2];
                #pragma unroll
                for (int mi = 0; mi < 4; mi++)
                    ldm4(arL[mi], tb + T_TB + offA + (uint32_t)(mi * 16 * ROWB) + kf);
                #pragma unroll
                for (int ni = 0; ni < 4; ni++)
                    ldm2(brL[ni], tb + 3 * T_TB + offB + (uint32_t)(ni * 8 * ROWB) + kf);
                #pragma unroll
                for (int mi = 0; mi < 4; mi++)
                    #pragma unroll
                    for (int ni = 0; ni < 4; ni++)
                        mma16816(acc[mi][ni], arH[mi], brL[ni]);
                #pragma unroll
                for (int mi = 0; mi < 4; mi++)
                    #pragma unroll
                    for (int ni = 0; ni < 4; ni++)
                        mma16816(acc[mi][ni], arL[mi], brH[ni]);
            }
        }
        __syncthreads();
        st++; if (st >= 3) st = 0;
    }

    // epilogue (row + col guarded)
    #pragma unroll
    for (int mi = 0; mi < 4; mi++) {
        long long r0 = m0 + wm * 64 + mi * 16 + (lane >> 2);
        bool vr0 = r0 < M, vr1 = (r0 + 8) < M;
        #pragma unroll
        for (int ni = 0; ni < 4; ni++) {
            int col = n0 + wn * 32 + ni * 8 + (lane & 3) * 2;
            float* a = acc[mi][ni];
            if (col < N) {
                long long o0 = r0 * (long long)ldc + col;
                long long o1 = (r0 + 8) * (long long)ldc + col;
                bool vc1 = (col + 1) < N;
                #pragma unroll
                for (int half = 0; half < 2; half++) {
                    bool vr = half ? vr1 : vr0;
                    if (!vr) continue;
                    long long o = half ? o1 : o0;
                    float v0 = alpha * a[half * 2];
                    float v1 = alpha * a[half * 2 + 1];
                    if (OM == 0) {
                        if (Res) v0 += Res[o];
                        C[o] = v0;
                        if (vc1) {
                            if (Res) v1 += Res[o + 1];
                            C[o + 1] = v1;
                        }
                    } else {
                        __nv_bfloat16 hh, ll;
                        split_bf(v0, hh, ll);
                        Ch[o] = hh; Cl[o] = ll;
                        if (vc1) {
                            split_bf(v1, hh, ll);
                            Ch[o + 1] = hh; Cl[o + 1] = ll;
                        }
                    }
                }
            }
        }
    }
}

// ------------------------------ host side ----------------------------------
static inline void run_mma(int split, int omode,
                           const __nv_bfloat16* Ah, const __nv_bfloat16* Al,
                           int lda, long long sA,
                           const __nv_bfloat16* Bh, const __nv_bfloat16* Bl,
                           int ldb, long long sB,
                           float* C, __nv_bfloat16* Ch, __nv_bfloat16* Cl,
                           int ldc, long long sC,
                           int M, int N, int K, float alpha,
                           const float* Res, long long sRes, int nb)
{
    dim3 grid((N + 127) / 128, (M + 127) / 128, nb);
    if (split == 3 && omode == 0)
        hmma_gemm_kernel<3, 0><<<grid, 256, GEMM_SMEM>>>(
            Ah, Al, lda, sA, Bh, Bl, ldb, sB, C, ldc, sC, Ch, Cl,
            M, N, K, alpha, Res, sRes);
    else if (split == 3 && omode == 1)
        hmma_gemm_kernel<3, 1><<<grid, 256, GEMM_SMEM>>>(
            Ah, Al, lda, sA, Bh, Bl, ldb, sB, C, ldc, sC, Ch, Cl,
            M, N, K, alpha, Res, sRes);
    else
        hmma_gemm_kernel<1, 0><<<grid, 256, GEMM_SMEM>>>(
            Ah, Al, lda, sA, Bh, Bl, ldb, sB, C, ldc, sC, Ch, Cl,
            M, N, K, alpha, Res, sRes);
}

extern "C" void kernel_launch(void* const* d_in, const int* in_sizes, int n_in,
                              void* d_out, int out_size)
{
    const float* x     = (const float*)d_in[0];
    const float* Wqkv  = (const float*)d_in[1];
    const float* Wq    = (const float*)d_in[2];
    const float* Wk    = (const float*)d_in[3];
    const float* Wv    = (const float*)d_in[4];
    const float* Wout  = (const float*)d_in[5];
    const float* gamma = (const float*)d_in[6];
    const float* beta  = (const float*)d_in[7];
    float* out = (float*)d_out;

    static int smem_set = 0;
    if (!smem_set) {
        cudaFuncSetAttribute(hmma_gemm_kernel<3, 0>,
                             cudaFuncAttributeMaxDynamicSharedMemorySize,
                             GEMM_SMEM);
        cudaFuncSetAttribute(hmma_gemm_kernel<3, 1>,
                             cudaFuncAttributeMaxDynamicSharedMemorySize,
                             GEMM_SMEM);
        cudaFuncSetAttribute(hmma_gemm_kernel<1, 0>,
                             cudaFuncAttributeMaxDynamicSharedMemorySize,
                             GEMM_SMEM);
        smem_set = 1;
    }

    float* fb = nullptr;
    __nv_bfloat16* hb = nullptr;
    cudaGetSymbolAddress((void**)&fb, g_buf);
    cudaGetSymbolAddress((void**)&hb, g_hb);

    float*  scores = fb + F_SC;
    float*  qa     = fb + F_QA;
    float*  ka     = fb + F_KA;
    float*  va     = fb + F_VA;
    float*  y_f    = fb + F_Y;
    float*  mqk_f  = fb + F_MQK;
    float*  wvo_f  = fb + F_WVO;
    float2* tw     = (float2*)(fb + F_TW);

    const long long sR = (long long)SEQ * RANKP;
    const long long sS = (long long)SEQ * SEQ;
    const float scale = 0.07905694150420949f;   // 1/sqrt(160)

    // 1. LayerNorm; twiddles; weight prep
    layernorm_kernel<<<BSROWS, 256>>>(x, gamma, beta, hb + H_XNH, hb + H_XNL);
    fill_twiddle_kernel<<<4, 256>>>(tw);
    transpose_split_kernel<<<dim3(31, 40), 256>>>(
        Wqkv, 1280, 975, hb + H_WQKVH, hb + H_WQKVL, 1280);
    split1_kernel<<<(416000 + 255) / 256, 256>>>(Wq, 416000LL,
                                                 hb + H_WQSH, hb + H_WQSL);
    split1_kernel<<<(416000 + 255) / 256, 256>>>(Wk, 416000LL,
                                                 hb + H_WKSH, hb + H_WKSL);
    split1_kernel<<<(416000 + 255) / 256, 256>>>(Wv, 416000LL,
                                                 hb + H_WVSH, hb + H_WVSL);
    transpose_split_kernel<<<dim3(40, 40), 256>>>(
        Wout, 1280, 1280, hb + H_WOTH, hb + H_WOTL, 1280);

    // 2. Precompute Mqk = Wq @ Wk^T, Wvo = Wv @ Wout (both exact split)
    run_mma(3, 0, hb + H_WQSH, hb + H_WQSL, 1280, 0,
            hb + H_WKSH, hb + H_WKSL, 1280, 0,
            mqk_f, nullptr, nullptr, 325, 0, 325, 325, 1280, 1.f, nullptr, 0, 1);
    run_mma(3, 0, hb + H_WVSH, hb + H_WVSL, 1280, 0,
            hb + H_WOTH, hb + H_WOTL, 1280, 0,
            wvo_f, nullptr, nullptr, 1280, 0, 325, 1280, 1280, 1.f,
            nullptr, 0, 1);
    transpose_split_kernel<<<dim3(11, 11), 256>>>(
        mqk_f, 325, 325, hb + H_MQKTH, hb + H_MQKTL, RANKP);
    transpose_split_kernel<<<dim3(40, 11), 256>>>(
        wvo_f, 325, 1280, hb + H_WVOTH, hb + H_WVOTL, RANKP);

    // 3. qkv_f = xn @ Wqkv (exact split)
    run_mma(3, 0, hb + H_XNH, hb + H_XNL, EDIM, 0,
            hb + H_WQKVH, hb + H_WQKVL, EDIM, 0,
            scores, nullptr, nullptr, N3R, 0, BSROWS, N3R, EDIM, 1.f,
            nullptr, 0, 1);

    // 4. split into fp32 qa/ka/va
    split3f_kernel<<<dim3(4, BSROWS), 256>>>(scores, qa, ka, va);

    // 5. FFT rank-space: qfa/kfa hi+lo (score path); vfaT hi only
    {
        dim3 g(RANKP / 4, BATCH);
        fft_cols_kernel<0, 1><<<g, 256>>>(qa, RANKP, hb + H_QFAH, hb + H_QFAL,
                                          tw, 1.0f);
        fft_cols_kernel<0, 1><<<g, 256>>>(ka, RANKP, hb + H_KFAH, hb + H_KFAL,
                                          tw, 1.0f);
        fft_cols_kernel<1, 0><<<g, 256>>>(va, RANKP, hb + H_VFATH, nullptr,
                                          tw, 1.0f);
    }

    // 6. sM = qfa @ Mqk (exact split, bf16 hi/lo out fused)
    run_mma(3, 1, hb + H_QFAH, hb + H_QFAL, RANKP, 0,
            hb + H_MQKTH, hb + H_MQKTL, RANKP, 0,
            nullptr, hb + H_SMH, hb + H_SML, RANKP, 0,
            BSROWS, RANKD, RANKP, 1.f, nullptr, 0, 1);

    // 7. scores = sM @ kfa^T / sqrt(160) (exact split)
    run_mma(3, 0, hb + H_SMH, hb + H_SML, RANKP, sR,
            hb + H_KFAH, hb + H_KFAL, RANKP, sR,
            scores, nullptr, nullptr, SEQ, sS, SEQ, SEQ, RANKP, scale,
            nullptr, 0, BATCH);

    // 8. attn = softmax(|scores|) -> bf16 hi only
    softmax_abs_kernel<<<BATCH * SEQ, 256>>>(scores, hb + H_ATH);

    // 9. y = attn @ vfa (single-pass bf16)
    run_mma(1, 0, hb + H_ATH, nullptr, SEQ, sS,
            hb + H_VFATH, nullptr, SEQ, sR,
            y_f, nullptr, nullptr, RANKP, sR, SEQ, RANKD, SEQ, 1.f,
            nullptr, 0, BATCH);

    // 10. z = Re(FFT(y))/2048 -> bf16 hi only
    {
        dim3 g(RANKP / 4, BATCH);
        fft_cols_kernel<0, 0><<<g, 256>>>(y_f, RANKP, hb + H_ZH, nullptr,
                                          tw, 1.0f / 2048.0f);
    }

    // 11. out = x + z @ Wvo (single-pass bf16)
    run_mma(1, 0, hb + H_ZH, nullptr, RANKP, 0,
            hb + H_WVOTH, nullptr, RANKP, 0,
            out, nullptr, nullptr, EDIM, 0, BSROWS, EDIM, RANKP, 1.f, x, 0, 1);
}

// round 15
// speedup vs baseline: 2.7673x; 1.0708x over previous
#include <cuda_runtime.h>
#include <cuda_bf16.h>
#include <math.h>
#include <stdint.h>

// ---------------------------------------------------------------------------
// RobustAttentionBlock (B=4, S=2048, E=1280, R=325) — rank-factored version
//
// scores = FFT(qa)·(Wq Wk^T)·FFT(ka)^T / sqrt(160)
// out    = x + IFFT(attn·FFT(va)) · (Wv·W_out)
// Score path: exact bf16 2-way split (3 mma passes). Post-softmax path:
// single-pass bf16 (proj ~8% of output norm -> ~4e-4 final rel err).
// R14: thresholded __expf softmax (scores are near-argmax; >99.9% underflow),
//      split3 fused into qkv GEMM epilogue, fused q/k/v FFT launch.
// ---------------------------------------------------------------------------

#define EDIM   1280
#define SEQ    2048
#define BATCH  4
#define RANKD  325
#define RANKP  328
#define N3R    975
#define BSROWS (BATCH * SEQ)

// ------------------------- fp32 scratch ------------------------------------
#define F_SC   0LL                                  // scores
#define F_QA   (F_SC  + 4LL*2048*2048)
#define F_KA   (F_QA  + 8192LL*RANKP)
#define F_VA   (F_KA  + 8192LL*RANKP)
#define F_Y    (F_VA  + 8192LL*RANKP)               // 4 x 2048 x 328
#define F_MQK  (F_Y   + 8192LL*RANKP)               // 325 x 325
#define F_WVO  (F_MQK + 105632LL)                   // 325 x 1280
#define F_TW   (F_WVO + 416000LL)
#define F_TOT  (F_TW  + 2048LL)
__device__ float g_buf[F_TOT];

// ------------------------- bf16 scratch ------------------------------------
#define SZ_T    (8192LL*1280)
#define SZ_R    (8192LL*RANKP)
#define SZ_SC   (4LL*2048*2048)
#define H_XNH    0LL
#define H_XNL    (H_XNH   + SZ_T)
#define H_WQKVH  (H_XNL   + SZ_T)
#define H_WQKVL  (H_WQKVH + 975LL*1280)
#define H_WQSH   (H_WQKVL + 975LL*1280)
#define H_WQSL   (H_WQSH  + 416000LL)
#define H_WKSH   (H_WQSL  + 416000LL)
#define H_WKSL   (H_WKSH  + 416000LL)
#define H_WVSH   (H_WKSL  + 416000LL)
#define H_WVSL   (H_WVSH  + 416000LL)
#define H_WOTH   (H_WVSL  + 416000LL)
#define H_WOTL   (H_WOTH  + 1280LL*1280)
#define H_MQKTH  (H_WOTL  + 1280LL*1280)
#define H_MQKTL  (H_MQKTH + 325LL*RANKP)
#define H_WVOTH  (H_MQKTL + 325LL*RANKP)
#define H_WVOTL  (H_WVOTH + 1280LL*RANKP)
#define H_QFAH   (H_WVOTL + 1280LL*RANKP)
#define H_QFAL   (H_QFAH  + SZ_R)
#define H_KFAH   (H_QFAL  + SZ_R)
#define H_KFAL   (H_KFAH  + SZ_R)
#define H_VFATH  (H_KFAL  + SZ_R)    // per batch: 328 x 2048 (hi only)
#define H_SMH    (H_VFATH + SZ_R)
#define H_SML    (H_SMH   + SZ_R)
#define H_ATH    (H_SML   + SZ_R)    // attn hi only
#define H_ZH     (H_ATH   + SZ_SC)
#define H_TOT    (H_ZH    + SZ_R)
__device__ __nv_bfloat16 g_hb[H_TOT];

// ------------------------------ PTX helpers --------------------------------
__device__ __forceinline__ uint32_t smem_u32(const void* p) {
    uint32_t a;
    asm("{ .reg .u64 t; cvta.to.shared.u64 t, %1; cvt.u32.u64 %0, t; }"
        : "=r"(a) : "l"(p));
    return a;
}
__device__ __forceinline__ void cp_async16(uint32_t sa, const void* g, int ssz) {
    asm volatile("cp.async.ca.shared.global [%0], [%1], 16, %2;"
                 :: "r"(sa), "l"(g), "r"(ssz) : "memory");
}
__device__ __forceinline__ void cp_commit() {
    asm volatile("cp.async.commit_group;" ::: "memory");
}
template <int NG>
__device__ __forceinline__ void cp_wait() {
    asm volatile("cp.async.wait_group %0;" :: "n"(NG) : "memory");
}
__device__ __forceinline__ void ldm4(uint32_t* r, uint32_t a) {
    asm volatile("ldmatrix.sync.aligned.m8n8.x4.shared.b16 {%0,%1,%2,%3}, [%4];"
                 : "=r"(r[0]), "=r"(r[1]), "=r"(r[2]), "=r"(r[3]) : "r"(a));
}
__device__ __forceinline__ void ldm2(uint32_t* r, uint32_t a) {
    asm volatile("ldmatrix.sync.aligned.m8n8.x2.shared.b16 {%0,%1}, [%2];"
                 : "=r"(r[0]), "=r"(r[1]) : "r"(a));
}
__device__ __forceinline__ void mma16816(float* c, const uint32_t* a,
                                         const uint32_t* b) {
    asm volatile(
        "mma.sync.aligned.m16n8k16.row.col.f32.bf16.bf16.f32 "
        "{%0,%1,%2,%3}, {%4,%5,%6,%7}, {%8,%9}, {%0,%1,%2,%3};"
        : "+f"(c[0]), "+f"(c[1]), "+f"(c[2]), "+f"(c[3])
        : "r"(a[0]), "r"(a[1]), "r"(a[2]), "r"(a[3]), "r"(b[0]), "r"(b[1]));
}

__device__ __forceinline__ void split_bf(float v, __nv_bfloat16& h, __nv_bfloat16& l) {
    h = __float2bfloat16(v);
    l = __float2bfloat16(v - __bfloat162float(h));
}

// ------------------------------ reductions ---------------------------------
__device__ __forceinline__ float warpReduceSum(float v) {
    #pragma unroll
    for (int o = 16; o > 0; o >>= 1) v += __shfl_xor_sync(0xffffffffu, v, o);
    return v;
}
__device__ __forceinline__ float warpReduceMax(float v) {
    #pragma unroll
    for (int o = 16; o > 0; o >>= 1) v = fmaxf(v, __shfl_xor_sync(0xffffffffu, v, o));
    return v;
}

// ------------------------------ layernorm -> bf16 hi/lo --------------------
__global__ __launch_bounds__(256) void layernorm_kernel(
    const float* __restrict__ x, const float* __restrict__ gamma,
    const float* __restrict__ beta,
    __nv_bfloat16* __restrict__ yh, __nv_bfloat16* __restrict__ yl)
{
    long long row = blockIdx.x;
    const float* xr = x + row * EDIM;

    float s = 0.f, s2 = 0.f;
    for (int i = threadIdx.x; i < EDIM; i += 256) {
        float v = xr[i];
        s += v; s2 += v * v;
    }
    __shared__ float sh[64];
    s  = warpReduceSum(s);
    s2 = warpReduceSum(s2);
    int w = threadIdx.x >> 5, l = threadIdx.x & 31;
    if (l == 0) { sh[w] = s; sh[32 + w] = s2; }
    __syncthreads();
    if (w == 0) {
        float a = (l < 8) ? sh[l] : 0.f;
        float b = (l < 8) ? sh[32 + l] : 0.f;
        a = warpReduceSum(a);
        b = warpReduceSum(b);
        if (l == 0) { sh[0] = a; sh[1] = b; }
    }
    __syncthreads();
    float mean = sh[0] * (1.0f / EDIM);
    float var  = sh[1] * (1.0f / EDIM) - mean * mean;
    float inv  = rsqrtf(var + 1e-5f);
    for (int i = threadIdx.x; i < EDIM; i += 256) {
        float v = (xr[i] - mean) * inv * gamma[i] + beta[i];
        __nv_bfloat16 h, lo; split_bf(v, h, lo);
        yh[row * EDIM + i] = h;
        yl[row * EDIM + i] = lo;
    }
}

// ------------------------------ twiddles -----------------------------------
__global__ void fill_twiddle_kernel(float2* __restrict__ tw)
{
    int k = blockIdx.x * 256 + threadIdx.x;
    if (k < 1024) {
        double ang = -6.283185307179586476925286766559 * (double)k / 2048.0;
        tw[k] = make_float2((float)cos(ang), (float)sin(ang));
    }
}

// ------------------------- transpose + split -------------------------------
__global__ __launch_bounds__(256) void transpose_split_kernel(
    const float* __restrict__ src, int R, int C,
    __nv_bfloat16* __restrict__ dh, __nv_bfloat16* __restrict__ dl, int dld)
{
    __shared__ float t[32][33];
    int c0 = blockIdx.x * 32, r0 = blockIdx.y * 32;
    int tx = threadIdx.x & 31, ty = threadIdx.x >> 5;
    for (int j = ty; j < 32; j += 8) {
        int y = r0 + j, xx = c0 + tx;
        t[j][tx] = (y < R && xx < C) ? src[(long long)y * C + xx] : 0.f;
    }
    __syncthreads();
    for (int j = ty; j < 32; j += 8) {
        int dr = c0 + j;
        int dc = r0 + tx;
        if (dr < C && dc < R) {
            __nv_bfloat16 h, lo; split_bf(t[tx][j], h, lo);
            dh[(long long)dr * dld + dc] = h;
            dl[(long long)dr * dld + dc] = lo;
        }
    }
}

// ------------------------- elementwise split -------------------------------
__global__ __launch_bounds__(256) void split1_kernel(
    const float* __restrict__ src, long long n,
    __nv_bfloat16* __restrict__ h, __nv_bfloat16* __restrict__ l)
{
    long long i = (long long)blockIdx.x * 256 + threadIdx.x;
    if (i >= n) return;
    __nv_bfloat16 hh, ll; split_bf(src[i], hh, ll);
    h[i] = hh; l[i] = ll;
}

// ------------------------------ FFT core -----------------------------------
__device__ __forceinline__ void fft_core(
    float2* z1, float2* z2, const float2* twz, int tid)
{
    for (int s = 0; s < 11; s++) {
        int half = 1 << s;
        for (int bb = tid; bb < 1024; bb += 256) {
            int pos = bb & (half - 1);
            int i0 = ((bb >> s) << (s + 1)) + pos;
            int i1 = i0 + half;
            float2 w = twz[pos << (10 - s)];
            float2 a, c; float tr, ti;
            a = z1[i0]; c = z1[i1];
            tr = w.x * c.x - w.y * c.y;
            ti = w.x * c.y + w.y * c.x;
            z1[i0] = make_float2(a.x + tr, a.y + ti);
            z1[i1] = make_float2(a.x - tr, a.y - ti);
            a = z2[i0]; c = z2[i1];
            tr = w.x * c.x - w.y * c.y;
            ti = w.x * c.y + w.y * c.x;
            z2[i0] = make_float2(a.x + tr, a.y + ti);
            z2[i1] = make_float2(a.x - tr, a.y - ti);
        }
        __syncthreads();
    }
}

// ---------------- fused q/k/v rank-space FFT (blockIdx.z selects) ----------
// z=0: qa -> qfa hi+lo (row layout); z=1: ka -> kfa hi+lo (row layout);
// z=2: va -> vfaT hi (transposed layout).
__global__ __launch_bounds__(256) void fft3_kernel(
    const float* __restrict__ qa, const float* __restrict__ ka,
    const float* __restrict__ va,
    __nv_bfloat16* __restrict__ qfh, __nv_bfloat16* __restrict__ qfl,
    __nv_bfloat16* __restrict__ kfh, __nv_bfloat16* __restrict__ kfl,
    __nv_bfloat16* __restrict__ vfth,
    const float2* __restrict__ tw)
{
    __shared__ float2 z1[SEQ];
    __shared__ float2 z2[SEQ];
    __shared__ float2 twz[1024];

    int col0 = blockIdx.x * 4;
    long long b = blockIdx.y;
    int which = blockIdx.z;
    const float* src = (which == 0) ? qa : (which == 1) ? ka : va;
    src += b * (long long)SEQ * RANKP + col0;
    int tid = threadIdx.x;

    for (int i = tid; i < 1024; i += 256) twz[i] = tw[i];

    for (int r = tid; r < SEQ; r += 256) {
        float4 v = *reinterpret_cast<const float4*>(src + (long long)r * RANKP);
        int br = __brev((unsigned)r) >> 21;
        z1[br] = make_float2(v.x, v.y);
        z2[br] = make_float2(v.z, v.w);
    }
    __syncthreads();

    fft_core(z1, z2, twz, tid);

    for (int r = tid; r < SEQ; r += 256) {
        int rr = (SEQ - r) & (SEQ - 1);
        float o0 = 0.5f * (z1[r].x + z1[rr].x);
        float o1 = 0.5f * (z1[r].y + z1[rr].y);
        float o2 = 0.5f * (z2[r].x + z2[rr].x);
        float o3 = 0.5f * (z2[r].y + z2[rr].y);
        if (which < 2) {
            __nv_bfloat16* oh = (which == 0) ? qfh : kfh;
            __nv_bfloat16* ol = (which == 0) ? qfl : kfl;
            long long off = b * (long long)SEQ * RANKP + (long long)r * RANKP + col0;
            __nv_bfloat16 h0,l0,h1,l1,h2,l2,h3,l3;
            split_bf(o0,h0,l0); split_bf(o1,h1,l1);
            split_bf(o2,h2,l2); split_bf(o3,h3,l3);
            oh[off+0]=h0; oh[off+1]=h1; oh[off+2]=h2; oh[off+3]=h3;
            ol[off+0]=l0; ol[off+1]=l1; ol[off+2]=l2; ol[off+3]=l3;
        } else {
            long long ob = b * (long long)RANKP * SEQ;
            vfth[ob + (long long)(col0+0)*SEQ + r] = __float2bfloat16(o0);
            vfth[ob + (long long)(col0+1)*SEQ + r] = __float2bfloat16(o1);
            vfth[ob + (long long)(col0+2)*SEQ + r] = __float2bfloat16(o2);
            vfth[ob + (long long)(col0+3)*SEQ + r] = __float2bfloat16(o3);
        }
    }
}

// ---------------- y -> z FFT (row layout, hi only) -------------------------
__global__ __launch_bounds__(256) void fft_z_kernel(
    const float* __restrict__ in, __nv_bfloat16* __restrict__ oh,
    const float2* __restrict__ tw, float scale)
{
    __shared__ float2 z1[SEQ];
    __shared__ float2 z2[SEQ];
    __shared__ float2 twz[1024];

    int col0 = blockIdx.x * 4;
    long long b = blockIdx.y;
    const float* src = in + b * (long long)SEQ * RANKP + col0;
    int tid = threadIdx.x;

    for (int i = tid; i < 1024; i += 256) twz[i] = tw[i];

    for (int r = tid; r < SEQ; r += 256) {
        float4 v = *reinterpret_cast<const float4*>(src + (long long)r * RANKP);
        int br = __brev((unsigned)r) >> 21;
        z1[br] = make_float2(v.x, v.y);
        z2[br] = make_float2(v.z, v.w);
    }
    __syncthreads();

    fft_core(z1, z2, twz, tid);

    float h = 0.5f * scale;
    for (int r = tid; r < SEQ; r += 256) {
        int rr = (SEQ - r) & (SEQ - 1);
        long long off = b * (long long)SEQ * RANKP + (long long)r * RANKP + col0;
        oh[off+0] = __float2bfloat16(h * (z1[r].x + z1[rr].x));
        oh[off+1] = __float2bfloat16(h * (z1[r].y + z1[rr].y));
        oh[off+2] = __float2bfloat16(h * (z2[r].x + z2[rr].x));
        oh[off+3] = __float2bfloat16(h * (z2[r].y + z2[rr].y));
    }
}

// ------------------------------ abs-softmax -> bf16 hi ---------------------
// Scores are near-argmax (std ~320): entries more than 16 below the max
// contribute < 1.2e-7 to the sum (>=1) -> treat as exact zero, skip MUFU.
__global__ __launch_bounds__(256) void softmax_abs_kernel(
    const float* __restrict__ s, __nv_bfloat16* __restrict__ ah)
{
    long long row = blockIdx.x;
    const float* sr = s + row * (long long)SEQ;
    float vals[8];
    float mx = -1e30f;
    #pragma unroll
    for (int i = 0; i < 8; i++) {
        float v = fabsf(sr[threadIdx.x + i * 256]);
        vals[i] = v;
        mx = fmaxf(mx, v);
    }
    __shared__ float sh[32];
    mx = warpReduceMax(mx);
    int w = threadIdx.x >> 5, l = threadIdx.x & 31;
    if (l == 0) sh[w] = mx;
    __syncthreads();
    if (w == 0) {
        float a = (l < 8) ? sh[l] : -1e30f;
        a = warpReduceMax(a);
        if (l == 0) sh[0] = a;
    }
    __syncthreads();
    float M = sh[0];
    float sum = 0.f;
    #pragma unroll
    for (int i = 0; i < 8; i++) {
        float xv = vals[i] - M;
        vals[i] = (xv > -16.f) ? __expf(xv) : 0.f;
        sum += vals[i];
    }
    __syncthreads();
    sum = warpReduceSum(sum);
    if (l == 0) sh[w] = sum;
    __syncthreads();
    if (w == 0) {
        float a = (l < 8) ? sh[l] : 0.f;
        a = warpReduceSum(a);
        if (l == 0) sh[0] = a;
    }
    __syncthreads();
    float inv = 1.0f / sh[0];
    #pragma unroll
    for (int i = 0; i < 8; i++) {
        long long off = row * (long long)SEQ + threadIdx.x + i * 256;
        ah[off] = __float2bfloat16(vals[i] * inv);
    }
}

// ------------------------------ HMMA GEMM ----------------------------------
// SPLIT=3: C=alpha*(Ah@Bh^T+Ah@Bl^T+Al@Bh^T); SPLIT=1: C=alpha*Ah@Bh^T.
// OM=0: fp32 C (+Res). OM=1: bf16 hi/lo (Ch,Cl). OM=2: fp32 qkv 3-way split
// (Ch->qa, Cl->ka, C->va as float*, columns 0/325/650, stride ldc=RANKP).
#define BKC     32
#define ROWB    80
#define T_TB    (128 * ROWB)
#define STAGEB  (4 * T_TB)
#define GEMM_SMEM (3 * STAGEB)   // 122880

__device__ __forceinline__ void load_tile_async(
    uint32_t tb, const __nv_bfloat16* __restrict__ src, long long row0,
    int ld, int nvalid, int kbase, int K, int tid)
{
    #pragma unroll
    for (int j = 0; j < 2; j++) {
        int row = (tid >> 2) + j * 64;
        int c = tid & 3;
        uint32_t sa = tb + row * ROWB + c * 16;
        const __nv_bfloat16* g = src + (row0 + row) * (long long)ld + kbase + c * 8;
        int ssz = (row < nvalid && (kbase + c * 8) < K) ? 16 : 0;
        cp_async16(sa, g, ssz);
    }
}

template <int SPLIT>
__device__ __forceinline__ void load_stage(
    uint32_t tb,
    const __nv_bfloat16* Ah, const __nv_bfloat16* Al, long long m0, int lda,
    int nvA,
    const __nv_bfloat16* Bh, const __nv_bfloat16* Bl, int n0, int ldb,
    int nvB, int kb, int K, int tid)
{
    load_tile_async(tb,            Ah, m0, lda, nvA, kb, K, tid);
    load_tile_async(tb + 2 * T_TB, Bh, n0, ldb, nvB, kb, K, tid);
    if (SPLIT == 3) {
        load_tile_async(tb + T_TB,     Al, m0, lda, nvA, kb, K, tid);
        load_tile_async(tb + 3 * T_TB, Bl, n0, ldb, nvB, kb, K, tid);
    }
}

template <int SPLIT, int OM>
__global__ void __launch_bounds__(256, 1) hmma_gemm_kernel(
    const __nv_bfloat16* __restrict__ Ah, const __nv_bfloat16* __restrict__ Al,
    int lda, long long sA,
    const __nv_bfloat16* __restrict__ Bh, const __nv_bfloat16* __restrict__ Bl,
    int ldb, long long sB,
    float* __restrict__ C, int ldc, long long sC,
    __nv_bfloat16* __restrict__ Ch, __nv_bfloat16* __restrict__ Cl,
    int M, int N, int K, float alpha,
    const float* __restrict__ Res, long long sRes)
{
    extern __shared__ char smem[];
    uint32_t sb = smem_u32(smem);
    int tid = threadIdx.x;
    int lane = tid & 31, w = tid >> 5;
    int wm = w & 1, wn = w >> 1;

    long long bz = blockIdx.z;
    Ah += bz * sA; if (SPLIT == 3) Al += bz * sA;
    Bh += bz * sB; if (SPLIT == 3) Bl += bz * sB;
    if (OM == 0) C += bz * sC;
    else if (OM == 1) { Ch += bz * sC; Cl += bz * sC; }
    if (Res) Res += bz * sRes;

    long long m0 = (long long)blockIdx.y * 128;
    int n0 = blockIdx.x * 128;
    int nvA = M - (int)m0; if (nvA > 128) nvA = 128;
    int nvB = N - n0; if (nvB > 128) nvB = 128;

    float acc[4][4][4];
    #pragma unroll
    for (int i = 0; i < 4; i++)
        #pragma unroll
        for (int j = 0; j < 4; j++)
            #pragma unroll
            for (int e = 0; e < 4; e++) acc[i][j][e] = 0.f;

    int l16 = lane & 15;
    uint32_t offA = (uint32_t)((wm * 64 + l16) * ROWB + ((lane >> 4) & 1) * 16);
    uint32_t offB = (uint32_t)((wn * 32 + (l16 & 7)) * ROWB + ((l16 >> 3) & 1) * 16);

    int nch = (K + BKC - 1) / BKC;

    load_stage<SPLIT>(sb, Ah, Al, m0, lda, nvA, Bh, Bl, n0, ldb, nvB, 0, K, tid);
    cp_commit();
    if (nch > 1) {
        load_stage<SPLIT>(sb + STAGEB, Ah, Al, m0, lda, nvA, Bh, Bl, n0, ldb,
                          nvB, BKC, K, tid);
    }
    cp_commit();

    int st = 0;
    for (int kt = 0; kt < nch; kt++) {
        if (kt + 2 < nch) {
            int st2 = st + 2; if (st2 >= 3) st2 -= 3;
            load_stage<SPLIT>(sb + st2 * STAGEB, Ah, Al, m0, lda, nvA, Bh, Bl,
                              n0, ldb, nvB, (kt + 2) * BKC, K, tid);
            cp_commit();
            cp_wait<2>();
        } else if (kt + 1 < nch) {
            cp_wait<1>();
        } else {
            cp_wait<0>();
        }
        __syncthreads();

        uint32_t tb = sb + st * STAGEB;
        #pragma unroll
        for (int ks = 0; ks < 2; ks++) {
            uint32_t kf = (uint32_t)(ks * 32);
            uint32_t arH[4][4], brH[4][2];
            #pragma unroll
            for (int mi = 0; mi < 4; mi++)
                ldm4(arH[mi], tb + offA + (uint32_t)(mi * 16 * ROWB) + kf);
            #pragma unroll
            for (int ni = 0; ni < 4; ni++)
                ldm2(brH[ni], tb + 2 * T_TB + offB + (uint32_t)(ni * 8 * ROWB) + kf);
            #pragma unroll
            for (int mi = 0; mi < 4; mi++)
                #pragma unroll
                for (int ni = 0; ni < 4; ni++)
                    mma16816(acc[mi][ni], arH[mi], brH[ni]);

            if (SPLIT == 3) {
                uint32_t arL[4][4], brL[4][2];
                #pragma unroll
                for (int mi = 0; mi < 4; mi++)
                    ldm4(arL[mi], tb + T_TB + offA + (uint32_t)(mi * 16 * ROWB) + kf);
                #pragma unroll
                for (int ni = 0; ni < 4; ni++)
                    ldm2(brL[ni], tb + 3 * T_TB + offB + (uint32_t)(ni * 8 * ROWB) + kf);
                #pragma unroll
                for (int mi = 0; mi < 4; mi++)
                    #pragma unroll
                    for (int ni = 0; ni < 4; ni++)
                        mma16816(acc[mi][ni], arH[mi], brL[ni]);
                #pragma unroll
                for (int mi = 0; mi < 4; mi++)
                    #pragma unroll
                    for (int ni = 0; ni < 4; ni++)
                        mma16816(acc[mi][ni], arL[mi], brH[ni]);
            }
        }
        __syncthreads();
        st++; if (st >= 3) st = 0;
    }

    // epilogue (row + col guarded)
    float* qaF = (float*)Ch;   // OM==2 aliases
    float* kaF = (float*)Cl;
    float* vaF = C;
    #pragma unroll
    for (int mi = 0; mi < 4; mi++) {
        long long r0 = m0 + wm * 64 + mi * 16 + (lane >> 2);
        #pragma unroll
        for (int ni = 0; ni < 4; ni++) {
            int col = n0 + wn * 32 + ni * 8 + (lane & 3) * 2;
            float* a = acc[mi][ni];
            #pragma unroll
            for (int half = 0; half < 2; half++) {
                long long r = r0 + half * 8;
                if (r >= M) continue;
                #pragma unroll
                for (int e = 0; e < 2; e++) {
                    int c = col + e;
                    if (c >= N) continue;
                    float v = alpha * a[half * 2 + e];
                    if (OM == 0) {
                        long long o = r * (long long)ldc + c;
                        if (Res) v += Res[o];
                        C[o] = v;
                    } else if (OM == 1) {
                        long long o = r * (long long)ldc + c;
                        __nv_bfloat16 hh, ll;
                        split_bf(v, hh, ll);
                        Ch[o] = hh; Cl[o] = ll;
                    } else {
                        int bsel = (c >= 650) ? 2 : (c >= 325 ? 1 : 0);
                        int cc = c - bsel * 325;
                        float* dst = (bsel == 0) ? qaF : (bsel == 1 ? kaF : vaF);
                        dst[r * (long long)ldc + cc] = v;
                    }
                }
            }
        }
    }
}

// ------------------------------ host side ----------------------------------
static inline void run_mma(int split, int omode,
                           const __nv_bfloat16* Ah, const __nv_bfloat16* Al,
                           int lda, long long sA,
                           const __nv_bfloat16* Bh, const __nv_bfloat16* Bl,
                           int ldb, long long sB,
                           float* C, __nv_bfloat16* Ch, __nv_bfloat16* Cl,
                           int ldc, long long sC,
                           int M, int N, int K, float alpha,
                           const float* Res, long long sRes, int nb)
{
    dim3 grid((N + 127) / 128, (M + 127) / 128, nb);
    if (split == 3 && omode == 0)
        hmma_gemm_kernel<3, 0><<<grid, 256, GEMM_SMEM>>>(
            Ah, Al, lda, sA, Bh, Bl, ldb, sB, C, ldc, sC, Ch, Cl,
            M, N, K, alpha, Res, sRes);
    else if (split == 3 && omode == 1)
        hmma_gemm_kernel<3, 1><<<grid, 256, GEMM_SMEM>>>(
            Ah, Al, lda, sA, Bh, Bl, ldb, sB, C, ldc, sC, Ch, Cl,
            M, N, K, alpha, Res, sRes);
    else if (split == 3 && omode == 2)
        hmma_gemm_kernel<3, 2><<<grid, 256, GEMM_SMEM>>>(
            Ah, Al, lda, sA, Bh, Bl, ldb, sB, C, ldc, sC, Ch, Cl,
            M, N, K, alpha, Res, sRes);
    else
        hmma_gemm_kernel<1, 0><<<grid, 256, GEMM_SMEM>>>(
            Ah, Al, lda, sA, Bh, Bl, ldb, sB, C, ldc, sC, Ch, Cl,
            M, N, K, alpha, Res, sRes);
}

extern "C" void kernel_launch(void* const* d_in, const int* in_sizes, int n_in,
                              void* d_out, int out_size)
{
    const float* x     = (const float*)d_in[0];
    const float* Wqkv  = (const float*)d_in[1];
    const float* Wq    = (const float*)d_in[2];
    const float* Wk    = (const float*)d_in[3];
    const float* Wv    = (const float*)d_in[4];
    const float* Wout  = (const float*)d_in[5];
    const float* gamma = (const float*)d_in[6];
    const float* beta  = (const float*)d_in[7];
    float* out = (float*)d_out;

    static int smem_set = 0;
    if (!smem_set) {
        cudaFuncSetAttribute(hmma_gemm_kernel<3, 0>,
                             cudaFuncAttributeMaxDynamicSharedMemorySize,
                             GEMM_SMEM);
        cudaFuncSetAttribute(hmma_gemm_kernel<3, 1>,
                             cudaFuncAttributeMaxDynamicSharedMemorySize,
                             GEMM_SMEM);
        cudaFuncSetAttribute(hmma_gemm_kernel<3, 2>,
                             cudaFuncAttributeMaxDynamicSharedMemorySize,
                             GEMM_SMEM);
        cudaFuncSetAttribute(hmma_gemm_kernel<1, 0>,
                             cudaFuncAttributeMaxDynamicSharedMemorySize,
                             GEMM_SMEM);
        smem_set = 1;
    }

    float* fb = nullptr;
    __nv_bfloat16* hb = nullptr;
    cudaGetSymbolAddress((void**)&fb, g_buf);
    cudaGetSymbolAddress((void**)&hb, g_hb);

    float*  scores = fb + F_SC;
    float*  qa     = fb + F_QA;
    float*  ka     = fb + F_KA;
    float*  va     = fb + F_VA;
    float*  y_f    = fb + F_Y;
    float*  mqk_f  = fb + F_MQK;
    float*  wvo_f  = fb + F_WVO;
    float2* tw     = (float2*)(fb + F_TW);

    const long long sR = (long long)SEQ * RANKP;
    const long long sS = (long long)SEQ * SEQ;
    const float scale = 0.07905694150420949f;   // 1/sqrt(160)

    // 1. LayerNorm; twiddles; weight prep
    layernorm_kernel<<<BSROWS, 256>>>(x, gamma, beta, hb + H_XNH, hb + H_XNL);
    fill_twiddle_kernel<<<4, 256>>>(tw);
    transpose_split_kernel<<<dim3(31, 40), 256>>>(
        Wqkv, 1280, 975, hb + H_WQKVH, hb + H_WQKVL, 1280);
    split1_kernel<<<(416000 + 255) / 256, 256>>>(Wq, 416000LL,
                                                 hb + H_WQSH, hb + H_WQSL);
    split1_kernel<<<(416000 + 255) / 256, 256>>>(Wk, 416000LL,
                                                 hb + H_WKSH, hb + H_WKSL);
    split1_kernel<<<(416000 + 255) / 256, 256>>>(Wv, 416000LL,
                                                 hb + H_WVSH, hb + H_WVSL);
    transpose_split_kernel<<<dim3(40, 40), 256>>>(
        Wout, 1280, 1280, hb + H_WOTH, hb + H_WOTL, 1280);

    // 2. Precompute Mqk = Wq @ Wk^T, Wvo = Wv @ Wout (exact split)
    run_mma(3, 0, hb + H_WQSH, hb + H_WQSL, 1280, 0,
            hb + H_WKSH, hb + H_WKSL, 1280, 0,
            mqk_f, nullptr, nullptr, 325, 0, 325, 325, 1280, 1.f, nullptr, 0, 1);
    run_mma(3, 0, hb + H_WVSH, hb + H_WVSL, 1280, 0,
            hb + H_WOTH, hb + H_WOTL, 1280, 0,
            wvo_f, nullptr, nullptr, 1280, 0, 325, 1280, 1280, 1.f,
            nullptr, 0, 1);
    transpose_split_kernel<<<dim3(11, 11), 256>>>(
        mqk_f, 325, 325, hb + H_MQKTH, hb + H_MQKTL, RANKP);
    transpose_split_kernel<<<dim3(40, 11), 256>>>(
        wvo_f, 325, 1280, hb + H_WVOTH, hb + H_WVOTL, RANKP);

    // 3. qkv = xn @ Wqkv with fused 3-way split into qa/ka/va (fp32)
    run_mma(3, 2, hb + H_XNH, hb + H_XNL, EDIM, 0,
            hb + H_WQKVH, hb + H_WQKVL, EDIM, 0,
            va, (__nv_bfloat16*)qa, (__nv_bfloat16*)ka, RANKP, 0,
            BSROWS, N3R, EDIM, 1.f, nullptr, 0, 1);

    // 4. fused rank-space FFTs: qfa/kfa hi+lo, vfaT hi
    fft3_kernel<<<dim3(RANKP / 4, BATCH, 3), 256>>>(
        qa, ka, va, hb + H_QFAH, hb + H_QFAL, hb + H_KFAH, hb + H_KFAL,
        hb + H_VFATH, tw);

    // 5. sM = qfa @ Mqk (exact split, bf16 hi/lo out fused)
    run_mma(3, 1, hb + H_QFAH, hb + H_QFAL, RANKP, 0,
            hb + H_MQKTH, hb + H_MQKTL, RANKP, 0,
            nullptr, hb + H_SMH, hb + H_SML, RANKP, 0,
            BSROWS, RANKD, RANKP, 1.f, nullptr, 0, 1);

    // 6. scores = sM @ kfa^T / sqrt(160) (exact split)
    run_mma(3, 0, hb + H_SMH, hb + H_SML, RANKP, sR,
            hb + H_KFAH, hb + H_KFAL, RANKP, sR,
            scores, nullptr, nullptr, SEQ, sS, SEQ, SEQ, RANKP, scale,
            nullptr, 0, BATCH);

    // 7. attn = softmax(|scores|) -> bf16 hi (thresholded __expf)
    softmax_abs_kernel<<<BATCH * SEQ, 256>>>(scores, hb + H_ATH);

    // 8. y = attn @ vfa (single-pass bf16)
    run_mma(1, 0, hb + H_ATH, nullptr, SEQ, sS,
            hb + H_VFATH, nullptr, SEQ, sR,
            y_f, nullptr, nullptr, RANKP, sR, SEQ, RANKD, SEQ, 1.f,
            nullptr, 0, BATCH);

    // 9. z = Re(FFT(y))/2048 -> bf16 hi
    fft_z_kernel<<<dim3(RANKP / 4, BATCH), 256>>>(y_f, hb + H_ZH, tw,
                                                  1.0f / 2048.0f);

    // 10. out = x + z @ Wvo (single-pass bf16)
    run_mma(1, 0, hb + H_ZH, nullptr, RANKP, 0,
            hb + H_WVOTH, nullptr, RANKP, 0,
            out, nullptr, nullptr, EDIM, 0, BSROWS, EDIM, RANKP, 1.f, x, 0, 1);
}

// round 17
// speedup vs baseline: 2.8668x; 1.0359x over previous
#include <cuda_runtime.h>
#include <cuda_bf16.h>
#include <math.h>
#include <stdint.h>

// ---------------------------------------------------------------------------
// RobustAttentionBlock (B=4, S=2048, E=1280, R=325) — rank-factored version
//
// scores = FFT(qa)·(Wq Wk^T)·FFT(ka)^T / sqrt(160)
// out    = x + IFFT(attn·FFT(va)) · (Wv·W_out)
// Score path: exact bf16 2-way split (3 mma passes). Post-softmax path:
// single-pass bf16. R16: SPLIT=1 GEMMs use compact 2-tile stages (61,440 B)
// + __launch_bounds__(256,2) reg cap -> guaranteed 2 CTAs/SM on attn@V/Wvo.
// ---------------------------------------------------------------------------

#define EDIM   1280
#define SEQ    2048
#define BATCH  4
#define RANKD  325
#define RANKP  328
#define N3R    975
#define BSROWS (BATCH * SEQ)

// ------------------------- fp32 scratch ------------------------------------
#define F_SC   0LL
#define F_QA   (F_SC  + 4LL*2048*2048)
#define F_KA   (F_QA  + 8192LL*RANKP)
#define F_VA   (F_KA  + 8192LL*RANKP)
#define F_Y    (F_VA  + 8192LL*RANKP)
#define F_MQK  (F_Y   + 8192LL*RANKP)
#define F_WVO  (F_MQK + 105632LL)
#define F_TW   (F_WVO + 416000LL)
#define F_TOT  (F_TW  + 2048LL)
__device__ float g_buf[F_TOT];

// ------------------------- bf16 scratch ------------------------------------
#define SZ_T    (8192LL*1280)
#define SZ_R    (8192LL*RANKP)
#define SZ_SC   (4LL*2048*2048)
#define H_XNH    0LL
#define H_XNL    (H_XNH   + SZ_T)
#define H_WQKVH  (H_XNL   + SZ_T)
#define H_WQKVL  (H_WQKVH + 975LL*1280)
#define H_WQSH   (H_WQKVL + 975LL*1280)
#define H_WQSL   (H_WQSH  + 416000LL)
#define H_WKSH   (H_WQSL  + 416000LL)
#define H_WKSL   (H_WKSH  + 416000LL)
#define H_WVSH   (H_WKSL  + 416000LL)
#define H_WVSL   (H_WVSH  + 416000LL)
#define H_WOTH   (H_WVSL  + 416000LL)
#define H_WOTL   (H_WOTH  + 1280LL*1280)
#define H_MQKTH  (H_WOTL  + 1280LL*1280)
#define H_MQKTL  (H_MQKTH + 325LL*RANKP)
#define H_WVOTH  (H_MQKTL + 325LL*RANKP)
#define H_WVOTL  (H_WVOTH + 1280LL*RANKP)
#define H_QFAH   (H_WVOTL + 1280LL*RANKP)
#define H_QFAL   (H_QFAH  + SZ_R)
#define H_KFAH   (H_QFAL  + SZ_R)
#define H_KFAL   (H_KFAH  + SZ_R)
#define H_VFATH  (H_KFAL  + SZ_R)
#define H_SMH    (H_VFATH + SZ_R)
#define H_SML    (H_SMH   + SZ_R)
#define H_ATH    (H_SML   + SZ_R)
#define H_ZH     (H_ATH   + SZ_SC)
#define H_TOT    (H_ZH    + SZ_R)
__device__ __nv_bfloat16 g_hb[H_TOT];

// ------------------------------ PTX helpers --------------------------------
__device__ __forceinline__ uint32_t smem_u32(const void* p) {
    uint32_t a;
    asm("{ .reg .u64 t; cvta.to.shared.u64 t, %1; cvt.u32.u64 %0, t; }"
        : "=r"(a) : "l"(p));
    return a;
}
__device__ __forceinline__ void cp_async16(uint32_t sa, const void* g, int ssz) {
    asm volatile("cp.async.ca.shared.global [%0], [%1], 16, %2;"
                 :: "r"(sa), "l"(g), "r"(ssz) : "memory");
}
__device__ __forceinline__ void cp_commit() {
    asm volatile("cp.async.commit_group;" ::: "memory");
}
template <int NG>
__device__ __forceinline__ void cp_wait() {
    asm volatile("cp.async.wait_group %0;" :: "n"(NG) : "memory");
}
__device__ __forceinline__ void ldm4(uint32_t* r, uint32_t a) {
    asm volatile("ldmatrix.sync.aligned.m8n8.x4.shared.b16 {%0,%1,%2,%3}, [%4];"
                 : "=r"(r[0]), "=r"(r[1]), "=r"(r[2]), "=r"(r[3]) : "r"(a));
}
__device__ __forceinline__ void ldm2(uint32_t* r, uint32_t a) {
    asm volatile("ldmatrix.sync.aligned.m8n8.x2.shared.b16 {%0,%1}, [%2];"
                 : "=r"(r[0]), "=r"(r[1]) : "r"(a));
}
__device__ __forceinline__ void mma16816(float* c, const uint32_t* a,
                                         const uint32_t* b) {
    asm volatile(
        "mma.sync.aligned.m16n8k16.row.col.f32.bf16.bf16.f32 "
        "{%0,%1,%2,%3}, {%4,%5,%6,%7}, {%8,%9}, {%0,%1,%2,%3};"
        : "+f"(c[0]), "+f"(c[1]), "+f"(c[2]), "+f"(c[3])
        : "r"(a[0]), "r"(a[1]), "r"(a[2]), "r"(a[3]), "r"(b[0]), "r"(b[1]));
}

__device__ __forceinline__ void split_bf(float v, __nv_bfloat16& h, __nv_bfloat16& l) {
    h = __float2bfloat16(v);
    l = __float2bfloat16(v - __bfloat162float(h));
}

// ------------------------------ reductions ---------------------------------
__device__ __forceinline__ float warpReduceSum(float v) {
    #pragma unroll
    for (int o = 16; o > 0; o >>= 1) v += __shfl_xor_sync(0xffffffffu, v, o);
    return v;
}
__device__ __forceinline__ float warpReduceMax(float v) {
    #pragma unroll
    for (int o = 16; o > 0; o >>= 1) v = fmaxf(v, __shfl_xor_sync(0xffffffffu, v, o));
    return v;
}

// ------------------------------ layernorm -> bf16 hi/lo --------------------
__global__ __launch_bounds__(256) void layernorm_kernel(
    const float* __restrict__ x, const float* __restrict__ gamma,
    const float* __restrict__ beta,
    __nv_bfloat16* __restrict__ yh, __nv_bfloat16* __restrict__ yl)
{
    long long row = blockIdx.x;
    const float* xr = x + row * EDIM;

    float s = 0.f, s2 = 0.f;
    for (int i = threadIdx.x; i < EDIM; i += 256) {
        float v = xr[i];
        s += v; s2 += v * v;
    }
    __shared__ float sh[64];
    s  = warpReduceSum(s);
    s2 = warpReduceSum(s2);
    int w = threadIdx.x >> 5, l = threadIdx.x & 31;
    if (l == 0) { sh[w] = s; sh[32 + w] = s2; }
    __syncthreads();
    if (w == 0) {
        float a = (l < 8) ? sh[l] : 0.f;
        float b = (l < 8) ? sh[32 + l] : 0.f;
        a = warpReduceSum(a);
        b = warpReduceSum(b);
        if (l == 0) { sh[0] = a; sh[1] = b; }
    }
    __syncthreads();
    float mean = sh[0] * (1.0f / EDIM);
    float var  = sh[1] * (1.0f / EDIM) - mean * mean;
    float inv  = rsqrtf(var + 1e-5f);
    for (int i = threadIdx.x; i < EDIM; i += 256) {
        float v = (xr[i] - mean) * inv * gamma[i] + beta[i];
        __nv_bfloat16 h, lo; split_bf(v, h, lo);
        yh[row * EDIM + i] = h;
        yl[row * EDIM + i] = lo;
    }
}

// ------------------------------ twiddles -----------------------------------
__global__ void fill_twiddle_kernel(float2* __restrict__ tw)
{
    int k = blockIdx.x * 256 + threadIdx.x;
    if (k < 1024) {
        double ang = -6.283185307179586476925286766559 * (double)k / 2048.0;
        tw[k] = make_float2((float)cos(ang), (float)sin(ang));
    }
}

// ------------------------- transpose + split -------------------------------
__global__ __launch_bounds__(256) void transpose_split_kernel(
    const float* __restrict__ src, int R, int C,
    __nv_bfloat16* __restrict__ dh, __nv_bfloat16* __restrict__ dl, int dld)
{
    __shared__ float t[32][33];
    int c0 = blockIdx.x * 32, r0 = blockIdx.y * 32;
    int tx = threadIdx.x & 31, ty = threadIdx.x >> 5;
    for (int j = ty; j < 32; j += 8) {
        int y = r0 + j, xx = c0 + tx;
        t[j][tx] = (y < R && xx < C) ? src[(long long)y * C + xx] : 0.f;
    }
    __syncthreads();
    for (int j = ty; j < 32; j += 8) {
        int dr = c0 + j;
        int dc = r0 + tx;
        if (dr < C && dc < R) {
            __nv_bfloat16 h, lo; split_bf(t[tx][j], h, lo);
            dh[(long long)dr * dld + dc] = h;
            dl[(long long)dr * dld + dc] = lo;
        }
    }
}

// ------------------------- elementwise split -------------------------------
__global__ __launch_bounds__(256) void split1_kernel(
    const float* __restrict__ src, long long n,
    __nv_bfloat16* __restrict__ h, __nv_bfloat16* __restrict__ l)
{
    long long i = (long long)blockIdx.x * 256 + threadIdx.x;
    if (i >= n) return;
    __nv_bfloat16 hh, ll; split_bf(src[i], hh, ll);
    h[i] = hh; l[i] = ll;
}

// ------------------------------ FFT core -----------------------------------
__device__ __forceinline__ void fft_core(
    float2* z1, float2* z2, const float2* twz, int tid)
{
    for (int s = 0; s < 11; s++) {
        int half = 1 << s;
        for (int bb = tid; bb < 1024; bb += 256) {
            int pos = bb & (half - 1);
            int i0 = ((bb >> s) << (s + 1)) + pos;
            int i1 = i0 + half;
            float2 w = twz[pos << (10 - s)];
            float2 a, c; float tr, ti;
            a = z1[i0]; c = z1[i1];
            tr = w.x * c.x - w.y * c.y;
            ti = w.x * c.y + w.y * c.x;
            z1[i0] = make_float2(a.x + tr, a.y + ti);
            z1[i1] = make_float2(a.x - tr, a.y - ti);
            a = z2[i0]; c = z2[i1];
            tr = w.x * c.x - w.y * c.y;
            ti = w.x * c.y + w.y * c.x;
            z2[i0] = make_float2(a.x + tr, a.y + ti);
            z2[i1] = make_float2(a.x - tr, a.y - ti);
        }
        __syncthreads();
    }
}

// ---------------- fused q/k/v rank-space FFT (blockIdx.z selects) ----------
__global__ __launch_bounds__(256) void fft3_kernel(
    const float* __restrict__ qa, const float* __restrict__ ka,
    const float* __restrict__ va,
    __nv_bfloat16* __restrict__ qfh, __nv_bfloat16* __restrict__ qfl,
    __nv_bfloat16* __restrict__ kfh, __nv_bfloat16* __restrict__ kfl,
    __nv_bfloat16* __restrict__ vfth,
    const float2* __restrict__ tw)
{
    __shared__ float2 z1[SEQ];
    __shared__ float2 z2[SEQ];
    __shared__ float2 twz[1024];

    int col0 = blockIdx.x * 4;
    long long b = blockIdx.y;
    int which = blockIdx.z;
    const float* src = (which == 0) ? qa : (which == 1) ? ka : va;
    src += b * (long long)SEQ * RANKP + col0;
    int tid = threadIdx.x;

    for (int i = tid; i < 1024; i += 256) twz[i] = tw[i];

    for (int r = tid; r < SEQ; r += 256) {
        float4 v = *reinterpret_cast<const float4*>(src + (long long)r * RANKP);
        int br = __brev((unsigned)r) >> 21;
        z1[br] = make_float2(v.x, v.y);
        z2[br] = make_float2(v.z, v.w);
    }
    __syncthreads();

    fft_core(z1, z2, twz, tid);

    for (int r = tid; r < SEQ; r += 256) {
        int rr = (SEQ - r) & (SEQ - 1);
        float o0 = 0.5f * (z1[r].x + z1[rr].x);
        float o1 = 0.5f * (z1[r].y + z1[rr].y);
        float o2 = 0.5f * (z2[r].x + z2[rr].x);
        float o3 = 0.5f * (z2[r].y + z2[rr].y);
        if (which < 2) {
            __nv_bfloat16* oh = (which == 0) ? qfh : kfh;
            __nv_bfloat16* ol = (which == 0) ? qfl : kfl;
            long long off = b * (long long)SEQ * RANKP + (long long)r * RANKP + col0;
            __nv_bfloat16 h0,l0,h1,l1,h2,l2,h3,l3;
            split_bf(o0,h0,l0); split_bf(o1,h1,l1);
            split_bf(o2,h2,l2); split_bf(o3,h3,l3);
            oh[off+0]=h0; oh[off+1]=h1; oh[off+2]=h2; oh[off+3]=h3;
            ol[off+0]=l0; ol[off+1]=l1; ol[off+2]=l2; ol[off+3]=l3;
        } else {
            long long ob = b * (long long)RANKP * SEQ;
            vfth[ob + (long long)(col0+0)*SEQ + r] = __float2bfloat16(o0);
            vfth[ob + (long long)(col0+1)*SEQ + r] = __float2bfloat16(o1);
            vfth[ob + (long long)(col0+2)*SEQ + r] = __float2bfloat16(o2);
            vfth[ob + (long long)(col0+3)*SEQ + r] = __float2bfloat16(o3);
        }
    }
}

// ---------------- y -> z FFT (row layout, hi only) -------------------------
__global__ __launch_bounds__(256) void fft_z_kernel(
    const float* __restrict__ in, __nv_bfloat16* __restrict__ oh,
    const float2* __restrict__ tw, float scale)
{
    __shared__ float2 z1[SEQ];
    __shared__ float2 z2[SEQ];
    __shared__ float2 twz[1024];

    int col0 = blockIdx.x * 4;
    long long b = blockIdx.y;
    const float* src = in + b * (long long)SEQ * RANKP + col0;
    int tid = threadIdx.x;

    for (int i = tid; i < 1024; i += 256) twz[i] = tw[i];

    for (int r = tid; r < SEQ; r += 256) {
        float4 v = *reinterpret_cast<const float4*>(src + (long long)r * RANKP);
        int br = __brev((unsigned)r) >> 21;
        z1[br] = make_float2(v.x, v.y);
        z2[br] = make_float2(v.z, v.w);
    }
    __syncthreads();

    fft_core(z1, z2, twz, tid);

    float h = 0.5f * scale;
    for (int r = tid; r < SEQ; r += 256) {
        int rr = (SEQ - r) & (SEQ - 1);
        long long off = b * (long long)SEQ * RANKP + (long long)r * RANKP + col0;
        oh[off+0] = __float2bfloat16(h * (z1[r].x + z1[rr].x));
        oh[off+1] = __float2bfloat16(h * (z1[r].y + z1[rr].y));
        oh[off+2] = __float2bfloat16(h * (z2[r].x + z2[rr].x));
        oh[off+3] = __float2bfloat16(h * (z2[r].y + z2[rr].y));
    }
}

// ------------------------------ abs-softmax -> bf16 hi ---------------------
__global__ __launch_bounds__(256) void softmax_abs_kernel(
    const float* __restrict__ s, __nv_bfloat16* __restrict__ ah)
{
    long long row = blockIdx.x;
    const float* sr = s + row * (long long)SEQ;
    float vals[8];
    float mx = -1e30f;
    #pragma unroll
    for (int i = 0; i < 8; i++) {
        float v = fabsf(sr[threadIdx.x + i * 256]);
        vals[i] = v;
        mx = fmaxf(mx, v);
    }
    __shared__ float sh[32];
    mx = warpReduceMax(mx);
    int w = threadIdx.x >> 5, l = threadIdx.x & 31;
    if (l == 0) sh[w] = mx;
    __syncthreads();
    if (w == 0) {
        float a = (l < 8) ? sh[l] : -1e30f;
        a = warpReduceMax(a);
        if (l == 0) sh[0] = a;
    }
    __syncthreads();
    float M = sh[0];
    float sum = 0.f;
    #pragma unroll
    for (int i = 0; i < 8; i++) {
        float xv = vals[i] - M;
        vals[i] = (xv > -16.f) ? __expf(xv) : 0.f;
        sum += vals[i];
    }
    __syncthreads();
    sum = warpReduceSum(sum);
    if (l == 0) sh[w] = sum;
    __syncthreads();
    if (w == 0) {
        float a = (l < 8) ? sh[l] : 0.f;
        a = warpReduceSum(a);
        if (l == 0) sh[0] = a;
    }
    __syncthreads();
    float inv = 1.0f / sh[0];
    #pragma unroll
    for (int i = 0; i < 8; i++) {
        long long off = row * (long long)SEQ + threadIdx.x + i * 256;
        ah[off] = __float2bfloat16(vals[i] * inv);
    }
}

// ------------------------------ HMMA GEMM ----------------------------------
// SPLIT=3: C=alpha*(Ah@Bh^T+Ah@Bl^T+Al@Bh^T); SPLIT=1: C=alpha*Ah@Bh^T.
// OM=0: fp32 C (+Res). OM=1: bf16 hi/lo (Ch,Cl). OM=2: fp32 qkv 3-way split.
// SPLIT=1: compact 2-tile stages (61,440 B) + minBlocks=2 reg cap -> 2 CTAs/SM.
#define BKC     32
#define ROWB    80
#define T_TB    (128 * ROWB)
#define SMEM_OF(s) (3 * ((s) == 3 ? 4 : 2) * T_TB)   // 122880 / 61440

__device__ __forceinline__ void load_tile_async(
    uint32_t tb, const __nv_bfloat16* __restrict__ src, long long row0,
    int ld, int nvalid, int kbase, int K, int tid)
{
    #pragma unroll
    for (int j = 0; j < 2; j++) {
        int row = (tid >> 2) + j * 64;
        int c = tid & 3;
        uint32_t sa = tb + row * ROWB + c * 16;
        const __nv_bfloat16* g = src + (row0 + row) * (long long)ld + kbase + c * 8;
        int ssz = (row < nvalid && (kbase + c * 8) < K) ? 16 : 0;
        cp_async16(sa, g, ssz);
    }
}

template <int SPLIT>
__device__ __forceinline__ void load_stage(
    uint32_t tb,
    const __nv_bfloat16* Ah, const __nv_bfloat16* Al, long long m0, int lda,
    int nvA,
    const __nv_bfloat16* Bh, const __nv_bfloat16* Bl, int n0, int ldb,
    int nvB, int kb, int K, int tid)
{
    const uint32_t BOFF = (SPLIT == 3 ? 2 : 1) * T_TB;
    load_tile_async(tb,        Ah, m0, lda, nvA, kb, K, tid);
    load_tile_async(tb + BOFF, Bh, n0, ldb, nvB, kb, K, tid);
    if (SPLIT == 3) {
        load_tile_async(tb + T_TB,        Al, m0, lda, nvA, kb, K, tid);
        load_tile_async(tb + BOFF + T_TB, Bl, n0, ldb, nvB, kb, K, tid);
    }
}

template <int SPLIT, int OM>
__global__ void __launch_bounds__(256, SPLIT == 1 ? 2 : 1) hmma_gemm_kernel(
    const __nv_bfloat16* __restrict__ Ah, const __nv_bfloat16* __restrict__ Al,
    int lda, long long sA,
    const __nv_bfloat16* __restrict__ Bh, const __nv_bfloat16* __restrict__ Bl,
    int ldb, long long sB,
    float* __restrict__ C, int ldc, long long sC,
    __nv_bfloat16* __restrict__ Ch, __nv_bfloat16* __restrict__ Cl,
    int M, int N, int K, float alpha,
    const float* __restrict__ Res, long long sRes)
{
    extern __shared__ char smem[];
    const uint32_t BOFF   = (SPLIT == 3 ? 2 : 1) * T_TB;
    const uint32_t STAGEB = (SPLIT == 3 ? 4 : 2) * T_TB;
    uint32_t sb = smem_u32(smem);
    int tid = threadIdx.x;
    int lane = tid & 31, w = tid >> 5;
    int wm = w & 1, wn = w >> 1;

    long long bz = blockIdx.z;
    Ah += bz * sA; if (SPLIT == 3) Al += bz * sA;
    Bh += bz * sB; if (SPLIT == 3) Bl += bz * sB;
    if (OM == 0) C += bz * sC;
    else if (OM == 1) { Ch += bz * sC; Cl += bz * sC; }
    if (Res) Res += bz * sRes;

    long long m0 = (long long)blockIdx.y * 128;
    int n0 = blockIdx.x * 128;
    int nvA = M - (int)m0; if (nvA > 128) nvA = 128;
    int nvB = N - n0; if (nvB > 128) nvB = 128;

    float acc[4][4][4];
    #pragma unroll
    for (int i = 0; i < 4; i++)
        #pragma unroll
        for (int j = 0; j < 4; j++)
            #pragma unroll
            for (int e = 0; e < 4; e++) acc[i][j][e] = 0.f;

    int l16 = lane & 15;
    uint32_t offA = (uint32_t)((wm * 64 + l16) * ROWB + ((lane >> 4) & 1) * 16);
    uint32_t offB = (uint32_t)((wn * 32 + (l16 & 7)) * ROWB + ((l16 >> 3) & 1) * 16);

    int nch = (K + BKC - 1) / BKC;

    load_stage<SPLIT>(sb, Ah, Al, m0, lda, nvA, Bh, Bl, n0, ldb, nvB, 0, K, tid);
    cp_commit();
    if (nch > 1) {
        load_stage<SPLIT>(sb + STAGEB, Ah, Al, m0, lda, nvA, Bh, Bl, n0, ldb,
                          nvB, BKC, K, tid);
    }
    cp_commit();

    int st = 0;
    for (int kt = 0; kt < nch; kt++) {
        if (kt + 2 < nch) {
            int st2 = st + 2; if (st2 >= 3) st2 -= 3;
            load_stage<SPLIT>(sb + st2 * STAGEB, Ah, Al, m0, lda, nvA, Bh, Bl,
                              n0, ldb, nvB, (kt + 2) * BKC, K, tid);
            cp_commit();
            cp_wait<2>();
        } else if (kt + 1 < nch) {
            cp_wait<1>();
        } else {
            cp_wait<0>();
        }
        __syncthreads();

        uint32_t tb = sb + st * STAGEB;
        #pragma unroll
        for (int ks = 0; ks < 2; ks++) {
            uint32_t kf = (uint32_t)(ks * 32);
            uint32_t arH[4][4], brH[4][2];
            #pragma unroll
            for (int mi = 0; mi < 4; mi++)
                ldm4(arH[mi], tb + offA + (uint32_t)(mi * 16 * ROWB) + kf);
            #pragma unroll
            for (int ni = 0; ni < 4; ni++)
                ldm2(brH[ni], tb + BOFF + offB + (uint32_t)(ni * 8 * ROWB) + kf);
            #pragma unroll
            for (int mi = 0; mi < 4; mi++)
                #pragma unroll
                for (int ni = 0; ni < 4; ni++)
                    mma16816(acc[mi][ni], arH[mi], brH[ni]);

            if (SPLIT == 3) {
                uint32_t arL[4][4], brL[4][2];
                #pragma unroll
                for (int mi = 0; mi < 4; mi++)
                    ldm4(arL[mi], tb + T_TB + offA + (uint32_t)(mi * 16 * ROWB) + kf);
                #pragma unroll
                for (int ni = 0; ni < 4; ni++)
                    ldm2(brL[ni], tb + BOFF + T_TB + offB + (uint32_t)(ni * 8 * ROWB) + kf);
                #pragma unroll
                for (int mi = 0; mi < 4; mi++)
                    #pragma unroll
                    for (int ni = 0; ni < 4; ni++)
                        mma16816(acc[mi][ni], arH[mi], brL[ni]);
                #pragma unroll
                for (int mi = 0; mi < 4; mi++)
                    #pragma unroll
                    for (int ni = 0; ni < 4; ni++)
                        mma16816(acc[mi][ni], arL[mi], brH[ni]);
            }
        }
        __syncthreads();
        st++; if (st >= 3) st = 0;
    }

    // epilogue (row + col guarded)
    float* qaF = (float*)Ch;   // OM==2 aliases
    float* kaF = (float*)Cl;
    float* vaF = C;
    #pragma unroll
    for (int mi = 0; mi < 4; mi++) {
        long long r0 = m0 + wm * 64 + mi * 16 + (lane >> 2);
        #pragma unroll
        for (int ni = 0; ni < 4; ni++) {
            int col = n0 + wn * 32 + ni * 8 + (lane & 3) * 2;
            float* a = acc[mi][ni];
            #pragma unroll
            for (int half = 0; half < 2; half++) {
                long long r = r0 + half * 8;
                if (r >= M) continue;
                #pragma unroll
                for (int e = 0; e < 2; e++) {
                    int c = col + e;
                    if (c >= N) continue;
                    float v = alpha * a[half * 2 + e];
                    if (OM == 0) {
                        long long o = r * (long long)ldc + c;
                        if (Res) v += Res[o];
                        C[o] = v;
                    } else if (OM == 1) {
                        long long o = r * (long long)ldc + c;
                        __nv_bfloat16 hh, ll;
                        split_bf(v, hh, ll);
                        Ch[o] = hh; Cl[o] = ll;
                    } else {
                        int bsel = (c >= 650) ? 2 : (c >= 325 ? 1 : 0);
                        int cc = c - bsel * 325;
                        float* dst = (bsel == 0) ? qaF : (bsel == 1 ? kaF : vaF);
                        dst[r * (long long)ldc + cc] = v;
                    }
                }
            }
        }
    }
}

// ------------------------------ host side ----------------------------------
static inline void run_mma(int split, int omode,
                           const __nv_bfloat16* Ah, const __nv_bfloat16* Al,
                           int lda, long long sA,
                           const __nv_bfloat16* Bh, const __nv_bfloat16* Bl,
                           int ldb, long long sB,
                           float* C, __nv_bfloat16* Ch, __nv_bfloat16* Cl,
                           int ldc, long long sC,
                           int M, int N, int K, float alpha,
                           const float* Res, long long sRes, int nb)
{
    dim3 grid((N + 127) / 128, (M + 127) / 128, nb);
    if (split == 3 && omode == 0)
        hmma_gemm_kernel<3, 0><<<grid, 256, SMEM_OF(3)>>>(
            Ah, Al, lda, sA, Bh, Bl, ldb, sB, C, ldc, sC, Ch, Cl,
            M, N, K, alpha, Res, sRes);
    else if (split == 3 && omode == 1)
        hmma_gemm_kernel<3, 1><<<grid, 256, SMEM_OF(3)>>>(
            Ah, Al, lda, sA, Bh, Bl, ldb, sB, C, ldc, sC, Ch, Cl,
            M, N, K, alpha, Res, sRes);
    else if (split == 3 && omode == 2)
        hmma_gemm_kernel<3, 2><<<grid, 256, SMEM_OF(3)>>>(
            Ah, Al, lda, sA, Bh, Bl, ldb, sB, C, ldc, sC, Ch, Cl,
            M, N, K, alpha, Res, sRes);
    else
        hmma_gemm_kernel<1, 0><<<grid, 256, SMEM_OF(1)>>>(
            Ah, Al, lda, sA, Bh, Bl, ldb, sB, C, ldc, sC, Ch, Cl,
            M, N, K, alpha, Res, sRes);
}

extern "C" void kernel_launch(void* const* d_in, const int* in_sizes, int n_in,
                              void* d_out, int out_size)
{
    const float* x     = (const float*)d_in[0];
    const float* Wqkv  = (const float*)d_in[1];
    const float* Wq    = (const float*)d_in[2];
    const float* Wk    = (const float*)d_in[3];
    const float* Wv    = (const float*)d_in[4];
    const float* Wout  = (const float*)d_in[5];
    const float* gamma = (const float*)d_in[6];
    const float* beta  = (const float*)d_in[7];
    float* out = (float*)d_out;

    static int smem_set = 0;
    if (!smem_set) {
        cudaFuncSetAttribute(hmma_gemm_kernel<3, 0>,
                             cudaFuncAttributeMaxDynamicSharedMemorySize,
                             SMEM_OF(3));
        cudaFuncSetAttribute(hmma_gemm_kernel<3, 1>,
                             cudaFuncAttributeMaxDynamicSharedMemorySize,
                             SMEM_OF(3));
        cudaFuncSetAttribute(hmma_gemm_kernel<3, 2>,
                             cudaFuncAttributeMaxDynamicSharedMemorySize,
                             SMEM_OF(3));
        cudaFuncSetAttribute(hmma_gemm_kernel<1, 0>,
                             cudaFuncAttributeMaxDynamicSharedMemorySize,
                             SMEM_OF(1));
        smem_set = 1;
    }

    float* fb = nullptr;
    __nv_bfloat16* hb = nullptr;
    cudaGetSymbolAddress((void**)&fb, g_buf);
    cudaGetSymbolAddress((void**)&hb, g_hb);

    float*  scores = fb + F_SC;
    float*  qa     = fb + F_QA;
    float*  ka     = fb + F_KA;
    float*  va     = fb + F_VA;
    float*  y_f    = fb + F_Y;
    float*  mqk_f  = fb + F_MQK;
    float*  wvo_f  = fb + F_WVO;
    float2* tw     = (float2*)(fb + F_TW);

    const long long sR = (long long)SEQ * RANKP;
    const long long sS = (long long)SEQ * SEQ;
    const float scale = 0.07905694150420949f;   // 1/sqrt(160)

    // 1. LayerNorm; twiddles; weight prep
    layernorm_kernel<<<BSROWS, 256>>>(x, gamma, beta, hb + H_XNH, hb + H_XNL);
    fill_twiddle_kernel<<<4, 256>>>(tw);
    transpose_split_kernel<<<dim3(31, 40), 256>>>(
        Wqkv, 1280, 975, hb + H_WQKVH, hb + H_WQKVL, 1280);
    split1_kernel<<<(416000 + 255) / 256, 256>>>(Wq, 416000LL,
                                                 hb + H_WQSH, hb + H_WQSL);
    split1_kernel<<<(416000 + 255) / 256, 256>>>(Wk, 416000LL,
                                                 hb + H_WKSH, hb + H_WKSL);
    split1_kernel<<<(416000 + 255) / 256, 256>>>(Wv, 416000LL,
                                                 hb + H_WVSH, hb + H_WVSL);
    transpose_split_kernel<<<dim3(40, 40), 256>>>(
        Wout, 1280, 1280, hb + H_WOTH, hb + H_WOTL, 1280);

    // 2. Precompute Mqk = Wq @ Wk^T, Wvo = Wv @ Wout (exact split)
    run_mma(3, 0, hb + H_WQSH, hb + H_WQSL, 1280, 0,
            hb + H_WKSH, hb + H_WKSL, 1280, 0,
            mqk_f, nullptr, nullptr, 325, 0, 325, 325, 1280, 1.f, nullptr, 0, 1);
    run_mma(3, 0, hb + H_WVSH, hb + H_WVSL, 1280, 0,
            hb + H_WOTH, hb + H_WOTL, 1280, 0,
            wvo_f, nullptr, nullptr, 1280, 0, 325, 1280, 1280, 1.f,
            nullptr, 0, 1);
    transpose_split_kernel<<<dim3(11, 11), 256>>>(
        mqk_f, 325, 325, hb + H_MQKTH, hb + H_MQKTL, RANKP);
    transpose_split_kernel<<<dim3(40, 11), 256>>>(
        wvo_f, 325, 1280, hb + H_WVOTH, hb + H_WVOTL, RANKP);

    // 3. qkv = xn @ Wqkv with fused 3-way split into qa/ka/va (fp32)
    run_mma(3, 2, hb + H_XNH, hb + H_XNL, EDIM, 0,
            hb + H_WQKVH, hb + H_WQKVL, EDIM, 0,
            va, (__nv_bfloat16*)qa, (__nv_bfloat16*)ka, RANKP, 0,
            BSROWS, N3R, EDIM, 1.f, nullptr, 0, 1);

    // 4. fused rank-space FFTs: qfa/kfa hi+lo, vfaT hi
    fft3_kernel<<<dim3(RANKP / 4, BATCH, 3), 256>>>(
        qa, ka, va, hb + H_QFAH, hb + H_QFAL, hb + H_KFAH, hb + H_KFAL,
        hb + H_VFATH, tw);

    // 5. sM = qfa @ Mqk (exact split, bf16 hi/lo out fused)
    run_mma(3, 1, hb + H_QFAH, hb + H_QFAL, RANKP, 0,
            hb + H_MQKTH, hb + H_MQKTL, RANKP, 0,
            nullptr, hb + H_SMH, hb + H_SML, RANKP, 0,
            BSROWS, RANKD, RANKP, 1.f, nullptr, 0, 1);

    // 6. scores = sM @ kfa^T / sqrt(160) (exact split)
    run_mma(3, 0, hb + H_SMH, hb + H_SML, RANKP, sR,
            hb + H_KFAH, hb + H_KFAL, RANKP, sR,
            scores, nullptr, nullptr, SEQ, sS, SEQ, SEQ, RANKP, scale,
            nullptr, 0, BATCH);

    // 7. attn = softmax(|scores|) -> bf16 hi (thresholded __expf)
    softmax_abs_kernel<<<BATCH * SEQ, 256>>>(scores, hb + H_ATH);

    // 8. y = attn @ vfa (single-pass bf16, 2 CTAs/SM)
    run_mma(1, 0, hb + H_ATH, nullptr, SEQ, sS,
            hb + H_VFATH, nullptr, SEQ, sR,
            y_f, nullptr, nullptr, RANKP, sR, SEQ, RANKD, SEQ, 1.f,
            nullptr, 0, BATCH);

    // 9. z = Re(FFT(y))/2048 -> bf16 hi
    fft_z_kernel<<<dim3(RANKP / 4, BATCH), 256>>>(y_f, hb + H_ZH, tw,
                                                  1.0f / 2048.0f);

    // 10. out = x + z @ Wvo (single-pass bf16, 2 CTAs/SM)
    run_mma(1, 0, hb + H_ZH, nullptr, RANKP, 0,
            hb + H_WVOTH, nullptr, RANKP, 0,
            out, nullptr, nullptr, EDIM, 0, BSROWS, EDIM, RANKP, 1.f, x, 0, 1);
}